// round 11
// baseline (speedup 1.0000x reference)
#include <cuda_runtime.h>
#include <cuda_fp16.h>
#include <math.h>

#define BB    256
#define AA    512
#define DDW   64
#define NPOS  (AA*DDW)
#define NTH   256
#define CH    8
#define ROWS  (AA/CH)
#define EPSF  1e-5f
#define FULLM 0xffffffffu

// fp16 scratch [b][a][d][*4]: y1/y2/y3 pre-LN conv outputs, x1 acts, v12 partial matvec
__device__ uint2  g_y1h[(size_t)BB*NPOS];
__device__ uint2  g_y2h[(size_t)BB*NPOS];
__device__ uint2  g_y3h[(size_t)BB*NPOS];
__device__ uint2  g_x1h[(size_t)BB*NPOS];
__device__ uint2  g_v12h[(size_t)BB*NPOS];
__device__ float  g_z [(size_t)BB*AA*16];
__device__ float2 g_p1[BB*CH], g_p2[BB*CH], g_p3[BB*CH];       // y-stats
__device__ float2 g_q1[BB*CH], g_q2[BB*CH], g_q3[BB*CH];       // x-stats (cat LN)

__device__ __forceinline__ float4 f4add(float4 a, float4 b){
  return make_float4(a.x+b.x, a.y+b.y, a.z+b.z, a.w+b.w);
}
__device__ __forceinline__ float dot4(float4 w, float4 v){
  return fmaf(w.x, v.x, fmaf(w.y, v.y, fmaf(w.z, v.z, w.w*v.w)));
}
// Branchless exact-enough GELU: Abramowitz-Stegun 7.1.26 erf (|err|<1.5e-7),
// reciprocal + exp on the MUFU pipe.
__device__ __forceinline__ float geluf(float x){
  float u = 0.70710678118654752440f * x;
  float a = fabsf(u);
  float t = __fdividef(1.f, fmaf(0.3275911f, a, 1.f));
  float e = __expf(-a*a);
  float p = fmaf(fmaf(fmaf(fmaf(1.061405429f, t, -1.453152027f), t,
              1.421413741f), t, -0.284496736f), t, 0.254829592f);
  float er = fmaf(-p*t, e, 1.f);
  er = copysignf(er, u);
  return 0.5f*x*(1.f + er);
}
__device__ __forceinline__ uint2 f4_to_h4(const float4& v){
  __half2 a = __floats2half2_rn(v.x, v.y);
  __half2 b = __floats2half2_rn(v.z, v.w);
  uint2 r;
  r.x = *reinterpret_cast<const unsigned int*>(&a);
  r.y = *reinterpret_cast<const unsigned int*>(&b);
  return r;
}
__device__ __forceinline__ float4 h4_to_f4(uint2 u){
  __half2 a = *reinterpret_cast<const __half2*>(&u.x);
  __half2 b = *reinterpret_cast<const __half2*>(&u.y);
  float2 f0 = __half22float2(a);
  float2 f1 = __half22float2(b);
  return make_float4(f0.x, f0.y, f1.x, f1.y);
}
__device__ __forceinline__ float4 ln4(float4 v, float m, float i){
  return make_float4((v.x-m)*i, (v.y-m)*i, (v.z-m)*i, (v.w-m)*i);
}
__device__ __forceinline__ float4 gelu_pw4(const float4* __restrict__ pw, float4 t){
  return make_float4(geluf(dot4(pw[0], t)), geluf(dot4(pw[1], t)),
                     geluf(dot4(pw[2], t)), geluf(dot4(pw[3], t)));
}
__device__ __forceinline__ float4 mv4(const float* __restrict__ W, float4 x){
  float o[4];
  #pragma unroll
  for (int p = 0; p < 4; p++){
    o[p] = fmaf(W[p*4+0], x.x, fmaf(W[p*4+1], x.y,
            fmaf(W[p*4+2], x.z, W[p*4+3]*x.w)));
  }
  return make_float4(o[0], o[1], o[2], o[3]);
}
__device__ __forceinline__ void loadConvW(const float* __restrict__ wp, float4 wk[3][4]){
  #pragma unroll
  for (int o = 0; o < 4; o++)
    #pragma unroll
    for (int k = 0; k < 3; k++)
      wk[k][o] = make_float4(wp[o*12 + 0 + k], wp[o*12 + 3 + k],
                             wp[o*12 + 6 + k], wp[o*12 + 9 + k]);
}
__device__ __forceinline__ float4 shflup2_4(float4 v){
  float4 r;
  r.x = __shfl_up_sync(FULLM, v.x, 2);
  r.y = __shfl_up_sync(FULLM, v.y, 2);
  r.z = __shfl_up_sync(FULLM, v.z, 2);
  r.w = __shfl_up_sync(FULLM, v.w, 2);
  return r;
}
__device__ __forceinline__ float4 shfldn2_4(float4 v){
  float4 r;
  r.x = __shfl_down_sync(FULLM, v.x, 2);
  r.y = __shfl_down_sync(FULLM, v.y, 2);
  r.z = __shfl_down_sync(FULLM, v.z, 2);
  r.w = __shfl_down_sync(FULLM, v.w, 2);
  return r;
}
__device__ __forceinline__ float4 shflsel4(float4 v, int sl){
  float4 r;
  r.x = __shfl_sync(FULLM, v.x, sl);
  r.y = __shfl_sync(FULLM, v.y, sl);
  r.z = __shfl_sync(FULLM, v.z, sl);
  r.w = __shfl_sync(FULLM, v.w, sl);
  return r;
}
struct Taps { float4 m0, p0, m1, p1; };
__device__ __forceinline__ Taps makeTaps(float4 T0, float4 T1, int lane){
  const float4 z4 = make_float4(0.f,0.f,0.f,0.f);
  Taps t;
  t.m0 = shflup2_4(T0);                 if (lane < 2)  t.m0 = z4;
  t.p0 = shflsel4((lane < 2) ? T1 : T0, (lane+2)  & 31);
  t.m1 = shflsel4((lane >= 30) ? T0 : T1, (lane-2) & 31);
  t.p1 = shfldn2_4(T1);                 if (lane >= 30) t.p1 = z4;
  return t;
}

__device__ __forceinline__ void blockReduceStore(float s, float q, float2* dst){
  #pragma unroll
  for (int off = 16; off > 0; off >>= 1){
    s += __shfl_xor_sync(FULLM, s, off);
    q += __shfl_xor_sync(FULLM, q, off);
  }
  __shared__ float red[16];
  int wp = threadIdx.x >> 5, ln = threadIdx.x & 31;
  if (ln == 0){ red[wp] = s; red[8+wp] = q; }
  __syncthreads();
  if (threadIdx.x == 0){
    float ss = 0.f, qq = 0.f;
    #pragma unroll
    for (int i = 0; i < 8; i++){ ss += red[i]; qq += red[8+i]; }
    *dst = make_float2(ss, qq);
  }
}
__device__ __forceinline__ void blockReduceStore2(float s1, float q1, float2* dst1,
                                                  float s2, float q2, float2* dst2){
  #pragma unroll
  for (int off = 16; off > 0; off >>= 1){
    s1 += __shfl_xor_sync(FULLM, s1, off);
    q1 += __shfl_xor_sync(FULLM, q1, off);
    s2 += __shfl_xor_sync(FULLM, s2, off);
    q2 += __shfl_xor_sync(FULLM, q2, off);
  }
  __shared__ float red[32];
  int wp = threadIdx.x >> 5, ln = threadIdx.x & 31;
  if (ln == 0){ red[wp] = s1; red[8+wp] = q1; red[16+wp] = s2; red[24+wp] = q2; }
  __syncthreads();
  if (threadIdx.x == 0){
    float a = 0.f, b = 0.f, c = 0.f, d = 0.f;
    #pragma unroll
    for (int i = 0; i < 8; i++){ a += red[i]; b += red[8+i]; c += red[16+i]; d += red[24+i]; }
    *dst1 = make_float2(a, b);
    *dst2 = make_float2(c, d);
  }
}
__device__ __forceinline__ void finalizeStats(const float2* __restrict__ part, int b,
                                              float invN, float& m, float& inv){
  float s = 0.f, q = 0.f;
  #pragma unroll
  for (int i = 0; i < CH; i++){
    float2 p = __ldg(&part[b*CH + i]);
    s += p.x; q += p.y;
  }
  m = s*invN;
  inv = rsqrtf(fmaf(-m, m, q*invN) + EPSF);
}
__device__ __forceinline__ void blockReduce2(float& s, float& q, volatile float* red){
  #pragma unroll
  for (int off = 16; off > 0; off >>= 1){
    s += __shfl_xor_sync(FULLM, s, off);
    q += __shfl_xor_sync(FULLM, q, off);
  }
  int wp = threadIdx.x >> 5, ln = threadIdx.x & 31;
  __syncthreads();
  if (ln == 0){ red[wp] = s; red[8+wp] = q; }
  __syncthreads();
  if (threadIdx.x == 0){
    float ss = 0.f, qq = 0.f;
    #pragma unroll
    for (int i = 0; i < 8; i++){ ss += red[i]; qq += red[8+i]; }
    red[16] = ss; red[17] = qq;
  }
  __syncthreads();
  s = red[16]; q = red[17];
}
__device__ __forceinline__ void acc8(float4 a, float4 b, float& sum, float& sq){
  sum += a.x+a.y+a.z+a.w + b.x+b.y+b.z+b.w;
  sq = fmaf(a.x,a.x, fmaf(a.y,a.y, fmaf(a.z,a.z, fmaf(a.w,a.w, sq))));
  sq = fmaf(b.x,b.x, fmaf(b.y,b.y, fmaf(b.z,b.z, fmaf(b.w,b.w, sq))));
}

#define INV_N1  (1.f/(4.f*(float)NPOS))
#define INV_N12 (1.f/(12.f*(float)NPOS))

// ============ K0: y1 = conv1(s) -> fp16; stats (raw fp32) ============
__global__ void __launch_bounds__(NTH, 3)
k_statsA(const float* __restrict__ s, const float* __restrict__ d1w1)
{
  const int b = blockIdx.x >> 3, chk = blockIdx.x & 7;
  const int lane = threadIdx.x & 31, warp = threadIdx.x >> 5;
  const size_t poff = (size_t)b*NPOS + (size_t)chk*ROWS*DDW;
  const float4* sb = reinterpret_cast<const float4*>(s + poff*4);
  uint2* y1b = g_y1h + poff;
  float4 wk[3][4]; loadConvW(d1w1, wk);
  float sum = 0.f, sq = 0.f;
  for (int r = 0; r < 8; ++r){
    int a = warp + 8*r;
    float4 T0 = sb[a*DDW + lane], T1 = sb[a*DDW + lane + 32];
    Taps tp = makeTaps(T0, T1, lane);
    float y0[4], y1[4];
    #pragma unroll
    for (int o = 0; o < 4; o++){
      y0[o] = dot4(wk[0][o], tp.m0) + dot4(wk[1][o], T0) + dot4(wk[2][o], tp.p0);
      y1[o] = dot4(wk[0][o], tp.m1) + dot4(wk[1][o], T1) + dot4(wk[2][o], tp.p1);
    }
    float4 Y0 = make_float4(y0[0], y0[1], y0[2], y0[3]);
    float4 Y1 = make_float4(y1[0], y1[1], y1[2], y1[3]);
    y1b[a*DDW + lane]      = f4_to_h4(Y0);
    y1b[a*DDW + lane + 32] = f4_to_h4(Y1);
    acc8(Y0, Y1, sum, sq);
  }
  blockReduceStore(sum, sq, &g_p1[blockIdx.x]);
}

// ============ K1: x1 = gelu(pw1(LN(y1h))) -> x1h; y2 = conv2(s+x1); x1 + y2 stats ============
__global__ void __launch_bounds__(NTH, 3)
k_passB(const float* __restrict__ s, const float* __restrict__ d1w2,
        const float* __restrict__ d2w1)
{
  __shared__ float4 sh_w2[12];
  __shared__ float4 sh_p1[4];
  const int b = blockIdx.x >> 3, chk = blockIdx.x & 7, tid = threadIdx.x;
  const int lane = tid & 31, warp = tid >> 5;
  const size_t poff = (size_t)b*NPOS + (size_t)chk*ROWS*DDW;
  const float4* sb  = reinterpret_cast<const float4*>(s + poff*4);
  const uint2*  y1b = g_y1h + poff;
  uint2*        x1b = g_x1h + poff;
  uint2*        y2b = g_y2h + poff;
  if (tid < 12){
    int k = tid >> 2, o = tid & 3;
    sh_w2[tid] = make_float4(d2w1[o*12+k], d2w1[o*12+3+k], d2w1[o*12+6+k], d2w1[o*12+9+k]);
  }
  if (tid < 4) sh_p1[tid] = make_float4(d1w2[tid*4+0], d1w2[tid*4+1], d1w2[tid*4+2], d1w2[tid*4+3]);
  float m1, i1; finalizeStats(g_p1, b, INV_N1, m1, i1);
  __syncthreads();

  float sum = 0.f, sq = 0.f;     // y2 stats
  float xs = 0.f, xq = 0.f;      // x1 stats (cat LN)
  for (int r = 0; r < 8; ++r){
    int a = warp + 8*r;
    float4 xv0 = gelu_pw4(sh_p1, ln4(h4_to_f4(y1b[a*DDW + lane]),      m1, i1));
    float4 xv1 = gelu_pw4(sh_p1, ln4(h4_to_f4(y1b[a*DDW + lane + 32]), m1, i1));
    x1b[a*DDW + lane]      = f4_to_h4(xv0);
    x1b[a*DDW + lane + 32] = f4_to_h4(xv1);
    acc8(xv0, xv1, xs, xq);
    float4 I0 = f4add(sb[a*DDW + lane],      xv0);
    float4 I1 = f4add(sb[a*DDW + lane + 32], xv1);
    Taps it = makeTaps(I0, I1, lane);
    float y0[4], y1[4];
    #pragma unroll
    for (int o = 0; o < 4; o++){
      y0[o] = dot4(sh_w2[o], it.m0) + dot4(sh_w2[4+o], I0) + dot4(sh_w2[8+o], it.p0);
      y1[o] = dot4(sh_w2[o], it.m1) + dot4(sh_w2[4+o], I1) + dot4(sh_w2[8+o], it.p1);
    }
    float4 Y0 = make_float4(y0[0], y0[1], y0[2], y0[3]);
    float4 Y1 = make_float4(y1[0], y1[1], y1[2], y1[3]);
    y2b[a*DDW + lane]      = f4_to_h4(Y0);
    y2b[a*DDW + lane + 32] = f4_to_h4(Y1);
    acc8(Y0, Y1, sum, sq);
  }
  blockReduceStore2(sum, sq, &g_p2[blockIdx.x], xs, xq, &g_q1[blockIdx.x]);
}

// ============ K2: x2; v12 = cwA*x1 + cwB*x2 -> v12h; y3 = conv3(s+x1+x2); x2 stats ============
__global__ void __launch_bounds__(NTH, 3)
k_passC(const float* __restrict__ s, const float* __restrict__ d2w2,
        const float* __restrict__ d3w1, const float* __restrict__ cw)
{
  __shared__ float4 sh_w3[12];
  __shared__ float4 sh_p2[4];
  __shared__ float  sh_cwA[16];
  __shared__ float  sh_cwB[16];
  const int b = blockIdx.x >> 3, chk = blockIdx.x & 7, tid = threadIdx.x;
  const int lane = tid & 31, warp = tid >> 5;
  const size_t poff = (size_t)b*NPOS + (size_t)chk*ROWS*DDW;
  const float4* sb  = reinterpret_cast<const float4*>(s + poff*4);
  const uint2*  x1b = g_x1h + poff;
  const uint2*  y2b = g_y2h + poff;
  uint2*        v12b = g_v12h + poff;
  uint2*        y3b = g_y3h + poff;
  if (tid < 12){
    int k = tid >> 2, o = tid & 3;
    sh_w3[tid] = make_float4(d3w1[o*12+k], d3w1[o*12+3+k], d3w1[o*12+6+k], d3w1[o*12+9+k]);
  }
  if (tid < 4) sh_p2[tid] = make_float4(d2w2[tid*4+0], d2w2[tid*4+1], d2w2[tid*4+2], d2w2[tid*4+3]);
  if (tid < 16){
    sh_cwA[tid] = cw[(tid >> 2)*12 + (tid & 3)];
    sh_cwB[tid] = cw[(tid >> 2)*12 + 4 + (tid & 3)];
  }
  float m2, i2; finalizeStats(g_p2, b, INV_N1, m2, i2);
  __syncthreads();

  float sum = 0.f, sq = 0.f;     // y3 stats
  float xs = 0.f, xq = 0.f;      // x2 stats
  for (int r = 0; r < 8; ++r){
    int a = warp + 8*r;
    float4 X0 = h4_to_f4(x1b[a*DDW + lane]);
    float4 X1 = h4_to_f4(x1b[a*DDW + lane + 32]);
    float4 xv0 = gelu_pw4(sh_p2, ln4(h4_to_f4(y2b[a*DDW + lane]),      m2, i2));
    float4 xv1 = gelu_pw4(sh_p2, ln4(h4_to_f4(y2b[a*DDW + lane + 32]), m2, i2));
    acc8(xv0, xv1, xs, xq);
    v12b[a*DDW + lane]      = f4_to_h4(f4add(mv4(sh_cwA, X0), mv4(sh_cwB, xv0)));
    v12b[a*DDW + lane + 32] = f4_to_h4(f4add(mv4(sh_cwA, X1), mv4(sh_cwB, xv1)));
    float4 I0 = f4add(f4add(sb[a*DDW + lane],      X0), xv0);
    float4 I1 = f4add(f4add(sb[a*DDW + lane + 32], X1), xv1);
    Taps it = makeTaps(I0, I1, lane);
    float y0[4], y1[4];
    #pragma unroll
    for (int o = 0; o < 4; o++){
      y0[o] = dot4(sh_w3[o], it.m0) + dot4(sh_w3[4+o], I0) + dot4(sh_w3[8+o], it.p0);
      y1[o] = dot4(sh_w3[o], it.m1) + dot4(sh_w3[4+o], I1) + dot4(sh_w3[8+o], it.p1);
    }
    float4 Y0 = make_float4(y0[0], y0[1], y0[2], y0[3]);
    float4 Y1 = make_float4(y1[0], y1[1], y1[2], y1[3]);
    y3b[a*DDW + lane]      = f4_to_h4(Y0);
    y3b[a*DDW + lane + 32] = f4_to_h4(Y1);
    acc8(Y0, Y1, sum, sq);
  }
  blockReduceStore2(sum, sq, &g_p3[blockIdx.x], xs, xq, &g_q2[blockIdx.x]);
}

// ============ K3: x3 from y3h; v = v12 + cwC*x3; zraw; x3 stats ============
__global__ void __launch_bounds__(NTH, 3)
k_passD(const float* __restrict__ d3w2, const float* __restrict__ cw,
        const float* __restrict__ c2w)
{
  __shared__ float2 sh_c2[16*4*32];
  __shared__ float  sh_cwC[16];
  __shared__ float4 sh_p3[4];
  const int b = blockIdx.x >> 3, chk = blockIdx.x & 7, tid = threadIdx.x;
  const int lane = tid & 31, warp = tid >> 5;
  const size_t poff = (size_t)b*NPOS + (size_t)chk*ROWS*DDW;
  const uint2*  y3b  = g_y3h + poff;
  const uint2*  v12b = g_v12h + poff;
  for (int k = tid; k < 2048; k += NTH){
    int l = k & 31, p = (k >> 5) & 3, o = k >> 7;
    sh_c2[k] = make_float2(c2w[o*256 + p*64 + l], c2w[o*256 + p*64 + l + 32]);
  }
  if (tid < 16) sh_cwC[tid] = cw[(tid >> 2)*12 + 8 + (tid & 3)];
  if (tid < 4) sh_p3[tid] = make_float4(d3w2[tid*4+0], d3w2[tid*4+1], d3w2[tid*4+2], d3w2[tid*4+3]);
  float m3, i3; finalizeStats(g_p3, b, INV_N1, m3, i3);
  __syncthreads();

  float xs = 0.f, xq = 0.f;
  for (int g = 0; g < 2; ++g){
    float V[4][2][4];
    #pragma unroll
    for (int r = 0; r < 4; ++r){
      int a = warp + 8*(4*g + r);
      float4 x30 = gelu_pw4(sh_p3, ln4(h4_to_f4(y3b[a*DDW + lane]),      m3, i3));
      float4 x31 = gelu_pw4(sh_p3, ln4(h4_to_f4(y3b[a*DDW + lane + 32]), m3, i3));
      acc8(x30, x31, xs, xq);
      float4 V0 = f4add(h4_to_f4(v12b[a*DDW + lane]),      mv4(sh_cwC, x30));
      float4 V1 = f4add(h4_to_f4(v12b[a*DDW + lane + 32]), mv4(sh_cwC, x31));
      V[r][0][0] = V0.x; V[r][0][1] = V0.y; V[r][0][2] = V0.z; V[r][0][3] = V0.w;
      V[r][1][0] = V1.x; V[r][1][1] = V1.y; V[r][1][2] = V1.z; V[r][1][3] = V1.w;
    }
    #pragma unroll
    for (int o = 0; o < 16; ++o){
      float2 wv[4];
      #pragma unroll
      for (int p = 0; p < 4; p++)
        wv[p] = sh_c2[(o*4 + p)*32 + lane];
      float acc[4];
      #pragma unroll
      for (int r = 0; r < 4; ++r){
        float a0 = 0.f;
        #pragma unroll
        for (int p = 0; p < 4; p++)
          a0 = fmaf(wv[p].x, V[r][0][p], fmaf(wv[p].y, V[r][1][p], a0));
        acc[r] = a0;
      }
      const bool b4 = (lane & 16) != 0, b3 = (lane & 8) != 0;
      float s0 = b4 ? acc[2] : acc[0];
      float s1 = b4 ? acc[3] : acc[1];
      s0 += __shfl_xor_sync(FULLM, b4 ? acc[0] : acc[2], 16);
      s1 += __shfl_xor_sync(FULLM, b4 ? acc[1] : acc[3], 16);
      float sv = b3 ? s1 : s0;
      sv += __shfl_xor_sync(FULLM, b3 ? s0 : s1, 8);
      sv += __shfl_xor_sync(FULLM, sv, 4);
      sv += __shfl_xor_sync(FULLM, sv, 2);
      sv += __shfl_xor_sync(FULLM, sv, 1);
      if ((lane & 7) == 0){
        int r = ((lane >> 4) << 1) | ((lane >> 3) & 1);
        int ag = chk*ROWS + warp + 8*(4*g + r);
        g_z[((size_t)b*AA + ag)*16 + o] = sv;
      }
    }
  }
  blockReduceStore(xs, xq, &g_q3[blockIdx.x]);
}

// ============ K4: affine-correct zraw -> LN -> +w -> 1x1(17->1) -> LN -> out ============
__global__ void __launch_bounds__(NTH)
k_final(const float* __restrict__ w, const float* __restrict__ cw,
        const float* __restrict__ c2w, const float* __restrict__ c3w,
        float* __restrict__ out)
{
  __shared__ float sh_z[AA*17];
  __shared__ float sh_red[18];
  __shared__ float sh_c3[17];
  __shared__ float sh_K[16];
  const int b = blockIdx.x, tid = threadIdx.x;
  if (tid < 17) sh_c3[tid] = c3w[tid];
  if (tid < 16){
    float csum[4];
    #pragma unroll
    for (int p = 0; p < 4; p++){
      float t = 0.f;
      #pragma unroll
      for (int c = 0; c < 12; c++) t += cw[p*12 + c];
      csum[p] = t;
    }
    float kk = 0.f;
    #pragma unroll
    for (int p = 0; p < 4; p++){
      const float* cb = c2w + tid*256 + p*64;
      float t = 0.f;
      for (int d = 0; d < 64; d++) t += cb[d];
      kk = fmaf(csum[p], t, kk);
    }
    sh_K[tid] = kk;
  }
  float cs = 0.f, cq = 0.f;
  #pragma unroll
  for (int i = 0; i < CH; i++){
    float2 a = __ldg(&g_q1[b*CH + i]);
    float2 c = __ldg(&g_q2[b*CH + i]);
    float2 d = __ldg(&g_q3[b*CH + i]);
    cs += a.x + c.x + d.x; cq += a.y + c.y + d.y;
  }
  float mc = cs*INV_N12;
  float icat = rsqrtf(fmaf(-mc, mc, cq*INV_N12) + EPSF);
  __syncthreads();

  const float4* zsrc = reinterpret_cast<const float4*>(g_z + (size_t)b*AA*16);
  float sz = 0.f, qz = 0.f;
  for (int idx = tid; idx < AA*4; idx += NTH){
    float4 v = zsrc[idx];
    int a = idx >> 2, o4 = (idx & 3)*4;
    v.x = icat*(v.x - mc*sh_K[o4+0]);
    v.y = icat*(v.y - mc*sh_K[o4+1]);
    v.z = icat*(v.z - mc*sh_K[o4+2]);
    v.w = icat*(v.w - mc*sh_K[o4+3]);
    float* dst = sh_z + a*17 + o4;
    dst[0] = v.x; dst[1] = v.y; dst[2] = v.z; dst[3] = v.w;
    sz += v.x+v.y+v.z+v.w;
    qz = fmaf(v.x,v.x, fmaf(v.y,v.y, fmaf(v.z,v.z, fmaf(v.w,v.w, qz))));
  }
  blockReduce2(sz, qz, sh_red);
  const float invN4 = 1.f/(16.f*(float)AA);
  float m4 = sz*invN4;
  float i4 = rsqrtf(fmaf(-m4, m4, qz*invN4) + EPSF);

  float rv[2]; float sr = 0.f, qr = 0.f;
  #pragma unroll
  for (int j = 0; j < 2; j++){
    int a = tid + j*NTH;
    float r = sh_c3[16]*w[(size_t)b*AA + a];
    const float* zr = sh_z + a*17;
    #pragma unroll
    for (int o = 0; o < 16; o++)
      r = fmaf(sh_c3[o], (zr[o] - m4)*i4, r);
    rv[j] = r; sr += r; qr = fmaf(r, r, qr);
  }
  blockReduce2(sr, qr, sh_red);
  float m5 = sr*(1.f/(float)AA);
  float i5 = rsqrtf(fmaf(-m5, m5, qr*(1.f/(float)AA)) + EPSF);
  #pragma unroll
  for (int j = 0; j < 2; j++)
    out[(size_t)b*AA + tid + j*NTH] = (rv[j] - m5)*i5;
}

extern "C" void kernel_launch(void* const* d_in, const int* in_sizes, int n_in,
                              void* d_out, int out_size)
{
  (void)in_sizes; (void)n_in; (void)out_size;
  const float* s    = (const float*)d_in[0];
  const float* w    = (const float*)d_in[1];
  const float* d1w1 = (const float*)d_in[2];
  const float* d1w2 = (const float*)d_in[3];
  const float* d2w1 = (const float*)d_in[4];
  const float* d2w2 = (const float*)d_in[5];
  const float* d3w1 = (const float*)d_in[6];
  const float* d3w2 = (const float*)d_in[7];
  const float* cw   = (const float*)d_in[8];
  const float* c2w  = (const float*)d_in[9];
  const float* c3w  = (const float*)d_in[10];
  float* out = (float*)d_out;

  k_statsA<<<BB*CH, NTH>>>(s, d1w1);
  k_passB <<<BB*CH, NTH>>>(s, d1w2, d2w1);
  k_passC <<<BB*CH, NTH>>>(s, d2w2, d3w1, cw);
  k_passD <<<BB*CH, NTH>>>(d3w2, cw, c2w);
  k_final <<<BB,    NTH>>>(w, cw, c2w, c3w, out);
}

// round 12
// speedup vs baseline: 1.0117x; 1.0117x over previous
#include <cuda_runtime.h>
#include <cuda_fp16.h>
#include <math.h>

#define BB    256
#define AA    512
#define DDW   64
#define NPOS  (AA*DDW)
#define NTH   256
#define CH    16
#define ROWS  (AA/CH)          // 32 rows per chunk
#define RITER (ROWS/8)         // 4 rows per warp
#define EPSF  1e-5f
#define FULLM 0xffffffffu

// fp16 scratch [b][a][d][*4]: y1/y2/y3 pre-LN conv outputs, x1 acts, v12 partial matvec
__device__ uint2  g_y1h[(size_t)BB*NPOS];
__device__ uint2  g_y2h[(size_t)BB*NPOS];
__device__ uint2  g_y3h[(size_t)BB*NPOS];
__device__ uint2  g_x1h[(size_t)BB*NPOS];
__device__ uint2  g_v12h[(size_t)BB*NPOS];
__device__ float  g_z [(size_t)BB*AA*16];
__device__ float2 g_p1[BB*CH], g_p2[BB*CH], g_p3[BB*CH];       // y-stats
__device__ float2 g_q1[BB*CH], g_q2[BB*CH], g_q3[BB*CH];       // x-stats (cat LN)

__device__ __forceinline__ float4 f4add(float4 a, float4 b){
  return make_float4(a.x+b.x, a.y+b.y, a.z+b.z, a.w+b.w);
}
__device__ __forceinline__ float dot4(float4 w, float4 v){
  return fmaf(w.x, v.x, fmaf(w.y, v.y, fmaf(w.z, v.z, w.w*v.w)));
}
__device__ __forceinline__ float geluf(float x){
  return 0.5f * x * (1.f + erff(x * 0.70710678118654752440f));
}
__device__ __forceinline__ uint2 f4_to_h4(const float4& v){
  __half2 a = __floats2half2_rn(v.x, v.y);
  __half2 b = __floats2half2_rn(v.z, v.w);
  uint2 r;
  r.x = *reinterpret_cast<const unsigned int*>(&a);
  r.y = *reinterpret_cast<const unsigned int*>(&b);
  return r;
}
__device__ __forceinline__ float4 h4_to_f4(uint2 u){
  __half2 a = *reinterpret_cast<const __half2*>(&u.x);
  __half2 b = *reinterpret_cast<const __half2*>(&u.y);
  float2 f0 = __half22float2(a);
  float2 f1 = __half22float2(b);
  return make_float4(f0.x, f0.y, f1.x, f1.y);
}
__device__ __forceinline__ float4 ln4(float4 v, float m, float i){
  return make_float4((v.x-m)*i, (v.y-m)*i, (v.z-m)*i, (v.w-m)*i);
}
__device__ __forceinline__ float4 gelu_pw4(const float4* __restrict__ pw, float4 t){
  return make_float4(geluf(dot4(pw[0], t)), geluf(dot4(pw[1], t)),
                     geluf(dot4(pw[2], t)), geluf(dot4(pw[3], t)));
}
__device__ __forceinline__ float4 mv4(const float* __restrict__ W, float4 x){
  float o[4];
  #pragma unroll
  for (int p = 0; p < 4; p++){
    o[p] = fmaf(W[p*4+0], x.x, fmaf(W[p*4+1], x.y,
            fmaf(W[p*4+2], x.z, W[p*4+3]*x.w)));
  }
  return make_float4(o[0], o[1], o[2], o[3]);
}
__device__ __forceinline__ void loadConvW(const float* __restrict__ wp, float4 wk[3][4]){
  #pragma unroll
  for (int o = 0; o < 4; o++)
    #pragma unroll
    for (int k = 0; k < 3; k++)
      wk[k][o] = make_float4(wp[o*12 + 0 + k], wp[o*12 + 3 + k],
                             wp[o*12 + 6 + k], wp[o*12 + 9 + k]);
}
__device__ __forceinline__ float4 shflup2_4(float4 v){
  float4 r;
  r.x = __shfl_up_sync(FULLM, v.x, 2);
  r.y = __shfl_up_sync(FULLM, v.y, 2);
  r.z = __shfl_up_sync(FULLM, v.z, 2);
  r.w = __shfl_up_sync(FULLM, v.w, 2);
  return r;
}
__device__ __forceinline__ float4 shfldn2_4(float4 v){
  float4 r;
  r.x = __shfl_down_sync(FULLM, v.x, 2);
  r.y = __shfl_down_sync(FULLM, v.y, 2);
  r.z = __shfl_down_sync(FULLM, v.z, 2);
  r.w = __shfl_down_sync(FULLM, v.w, 2);
  return r;
}
__device__ __forceinline__ float4 shflsel4(float4 v, int sl){
  float4 r;
  r.x = __shfl_sync(FULLM, v.x, sl);
  r.y = __shfl_sync(FULLM, v.y, sl);
  r.z = __shfl_sync(FULLM, v.z, sl);
  r.w = __shfl_sync(FULLM, v.w, sl);
  return r;
}
struct Taps { float4 m0, p0, m1, p1; };
__device__ __forceinline__ Taps makeTaps(float4 T0, float4 T1, int lane){
  const float4 z4 = make_float4(0.f,0.f,0.f,0.f);
  Taps t;
  t.m0 = shflup2_4(T0);                 if (lane < 2)  t.m0 = z4;
  t.p0 = shflsel4((lane < 2) ? T1 : T0, (lane+2)  & 31);
  t.m1 = shflsel4((lane >= 30) ? T0 : T1, (lane-2) & 31);
  t.p1 = shfldn2_4(T1);                 if (lane >= 30) t.p1 = z4;
  return t;
}

__device__ __forceinline__ void blockReduceStore(float s, float q, float2* dst){
  #pragma unroll
  for (int off = 16; off > 0; off >>= 1){
    s += __shfl_xor_sync(FULLM, s, off);
    q += __shfl_xor_sync(FULLM, q, off);
  }
  __shared__ float red[16];
  int wp = threadIdx.x >> 5, ln = threadIdx.x & 31;
  if (ln == 0){ red[wp] = s; red[8+wp] = q; }
  __syncthreads();
  if (threadIdx.x == 0){
    float ss = 0.f, qq = 0.f;
    #pragma unroll
    for (int i = 0; i < 8; i++){ ss += red[i]; qq += red[8+i]; }
    *dst = make_float2(ss, qq);
  }
}
__device__ __forceinline__ void blockReduceStore2(float s1, float q1, float2* dst1,
                                                  float s2, float q2, float2* dst2){
  #pragma unroll
  for (int off = 16; off > 0; off >>= 1){
    s1 += __shfl_xor_sync(FULLM, s1, off);
    q1 += __shfl_xor_sync(FULLM, q1, off);
    s2 += __shfl_xor_sync(FULLM, s2, off);
    q2 += __shfl_xor_sync(FULLM, q2, off);
  }
  __shared__ float red[32];
  int wp = threadIdx.x >> 5, ln = threadIdx.x & 31;
  if (ln == 0){ red[wp] = s1; red[8+wp] = q1; red[16+wp] = s2; red[24+wp] = q2; }
  __syncthreads();
  if (threadIdx.x == 0){
    float a = 0.f, b = 0.f, c = 0.f, d = 0.f;
    #pragma unroll
    for (int i = 0; i < 8; i++){ a += red[i]; b += red[8+i]; c += red[16+i]; d += red[24+i]; }
    *dst1 = make_float2(a, b);
    *dst2 = make_float2(c, d);
  }
}
__device__ __forceinline__ void finalizeStats(const float2* __restrict__ part, int b,
                                              float invN, float& m, float& inv){
  float s = 0.f, q = 0.f;
  #pragma unroll
  for (int i = 0; i < CH; i++){
    float2 p = __ldg(&part[b*CH + i]);
    s += p.x; q += p.y;
  }
  m = s*invN;
  inv = rsqrtf(fmaf(-m, m, q*invN) + EPSF);
}
__device__ __forceinline__ void blockReduce2(float& s, float& q, volatile float* red){
  #pragma unroll
  for (int off = 16; off > 0; off >>= 1){
    s += __shfl_xor_sync(FULLM, s, off);
    q += __shfl_xor_sync(FULLM, q, off);
  }
  int wp = threadIdx.x >> 5, ln = threadIdx.x & 31;
  __syncthreads();
  if (ln == 0){ red[wp] = s; red[8+wp] = q; }
  __syncthreads();
  if (threadIdx.x == 0){
    float ss = 0.f, qq = 0.f;
    #pragma unroll
    for (int i = 0; i < 8; i++){ ss += red[i]; qq += red[8+i]; }
    red[16] = ss; red[17] = qq;
  }
  __syncthreads();
  s = red[16]; q = red[17];
}
__device__ __forceinline__ void acc8(float4 a, float4 b, float& sum, float& sq){
  sum += a.x+a.y+a.z+a.w + b.x+b.y+b.z+b.w;
  sq = fmaf(a.x,a.x, fmaf(a.y,a.y, fmaf(a.z,a.z, fmaf(a.w,a.w, sq))));
  sq = fmaf(b.x,b.x, fmaf(b.y,b.y, fmaf(b.z,b.z, fmaf(b.w,b.w, sq))));
}

#define INV_N1  (1.f/(4.f*(float)NPOS))
#define INV_N12 (1.f/(12.f*(float)NPOS))

// ============ K0: y1 = conv1(s) -> fp16; stats ============
__global__ void __launch_bounds__(NTH, 3)
k_statsA(const float* __restrict__ s, const float* __restrict__ d1w1)
{
  const int b = blockIdx.x >> 4, chk = blockIdx.x & 15;
  const int lane = threadIdx.x & 31, warp = threadIdx.x >> 5;
  const size_t poff = (size_t)b*NPOS + (size_t)chk*ROWS*DDW;
  const float4* sb = reinterpret_cast<const float4*>(s + poff*4);
  uint2* y1b = g_y1h + poff;
  float4 wk[3][4]; loadConvW(d1w1, wk);
  float sum = 0.f, sq = 0.f;
  for (int r = 0; r < RITER; ++r){
    int a = warp + 8*r;
    float4 T0 = sb[a*DDW + lane], T1 = sb[a*DDW + lane + 32];
    Taps tp = makeTaps(T0, T1, lane);
    float y0[4], y1[4];
    #pragma unroll
    for (int o = 0; o < 4; o++){
      y0[o] = dot4(wk[0][o], tp.m0) + dot4(wk[1][o], T0) + dot4(wk[2][o], tp.p0);
      y1[o] = dot4(wk[0][o], tp.m1) + dot4(wk[1][o], T1) + dot4(wk[2][o], tp.p1);
    }
    float4 Y0 = make_float4(y0[0], y0[1], y0[2], y0[3]);
    float4 Y1 = make_float4(y1[0], y1[1], y1[2], y1[3]);
    y1b[a*DDW + lane]      = f4_to_h4(Y0);
    y1b[a*DDW + lane + 32] = f4_to_h4(Y1);
    acc8(Y0, Y1, sum, sq);
  }
  blockReduceStore(sum, sq, &g_p1[blockIdx.x]);
}

// ============ K1: x1 = gelu(pw1(LN(y1h))) -> x1h; y2 = conv2(s+x1); x1 + y2 stats ============
__global__ void __launch_bounds__(NTH, 3)
k_passB(const float* __restrict__ s, const float* __restrict__ d1w2,
        const float* __restrict__ d2w1)
{
  __shared__ float4 sh_w2[12];
  __shared__ float4 sh_p1[4];
  const int b = blockIdx.x >> 4, chk = blockIdx.x & 15, tid = threadIdx.x;
  const int lane = tid & 31, warp = tid >> 5;
  const size_t poff = (size_t)b*NPOS + (size_t)chk*ROWS*DDW;
  const float4* sb  = reinterpret_cast<const float4*>(s + poff*4);
  const uint2*  y1b = g_y1h + poff;
  uint2*        x1b = g_x1h + poff;
  uint2*        y2b = g_y2h + poff;
  if (tid < 12){
    int k = tid >> 2, o = tid & 3;
    sh_w2[tid] = make_float4(d2w1[o*12+k], d2w1[o*12+3+k], d2w1[o*12+6+k], d2w1[o*12+9+k]);
  }
  if (tid < 4) sh_p1[tid] = make_float4(d1w2[tid*4+0], d1w2[tid*4+1], d1w2[tid*4+2], d1w2[tid*4+3]);
  float m1, i1; finalizeStats(g_p1, b, INV_N1, m1, i1);
  __syncthreads();

  float sum = 0.f, sq = 0.f;
  float xs = 0.f, xq = 0.f;
  for (int r = 0; r < RITER; ++r){
    int a = warp + 8*r;
    float4 xv0 = gelu_pw4(sh_p1, ln4(h4_to_f4(y1b[a*DDW + lane]),      m1, i1));
    float4 xv1 = gelu_pw4(sh_p1, ln4(h4_to_f4(y1b[a*DDW + lane + 32]), m1, i1));
    x1b[a*DDW + lane]      = f4_to_h4(xv0);
    x1b[a*DDW + lane + 32] = f4_to_h4(xv1);
    acc8(xv0, xv1, xs, xq);
    float4 I0 = f4add(sb[a*DDW + lane],      xv0);
    float4 I1 = f4add(sb[a*DDW + lane + 32], xv1);
    Taps it = makeTaps(I0, I1, lane);
    float y0[4], y1[4];
    #pragma unroll
    for (int o = 0; o < 4; o++){
      y0[o] = dot4(sh_w2[o], it.m0) + dot4(sh_w2[4+o], I0) + dot4(sh_w2[8+o], it.p0);
      y1[o] = dot4(sh_w2[o], it.m1) + dot4(sh_w2[4+o], I1) + dot4(sh_w2[8+o], it.p1);
    }
    float4 Y0 = make_float4(y0[0], y0[1], y0[2], y0[3]);
    float4 Y1 = make_float4(y1[0], y1[1], y1[2], y1[3]);
    y2b[a*DDW + lane]      = f4_to_h4(Y0);
    y2b[a*DDW + lane + 32] = f4_to_h4(Y1);
    acc8(Y0, Y1, sum, sq);
  }
  blockReduceStore2(sum, sq, &g_p2[blockIdx.x], xs, xq, &g_q1[blockIdx.x]);
}

// ============ K2: x2; v12 = cwA*x1 + cwB*x2 -> v12h; y3 = conv3(s+x1+x2); x2 stats ============
__global__ void __launch_bounds__(NTH, 3)
k_passC(const float* __restrict__ s, const float* __restrict__ d2w2,
        const float* __restrict__ d3w1, const float* __restrict__ cw)
{
  __shared__ float4 sh_w3[12];
  __shared__ float4 sh_p2[4];
  __shared__ float  sh_cwA[16];
  __shared__ float  sh_cwB[16];
  const int b = blockIdx.x >> 4, chk = blockIdx.x & 15, tid = threadIdx.x;
  const int lane = tid & 31, warp = tid >> 5;
  const size_t poff = (size_t)b*NPOS + (size_t)chk*ROWS*DDW;
  const float4* sb  = reinterpret_cast<const float4*>(s + poff*4);
  const uint2*  x1b = g_x1h + poff;
  const uint2*  y2b = g_y2h + poff;
  uint2*        v12b = g_v12h + poff;
  uint2*        y3b = g_y3h + poff;
  if (tid < 12){
    int k = tid >> 2, o = tid & 3;
    sh_w3[tid] = make_float4(d3w1[o*12+k], d3w1[o*12+3+k], d3w1[o*12+6+k], d3w1[o*12+9+k]);
  }
  if (tid < 4) sh_p2[tid] = make_float4(d2w2[tid*4+0], d2w2[tid*4+1], d2w2[tid*4+2], d2w2[tid*4+3]);
  if (tid < 16){
    sh_cwA[tid] = cw[(tid >> 2)*12 + (tid & 3)];
    sh_cwB[tid] = cw[(tid >> 2)*12 + 4 + (tid & 3)];
  }
  float m2, i2; finalizeStats(g_p2, b, INV_N1, m2, i2);
  __syncthreads();

  float sum = 0.f, sq = 0.f;
  float xs = 0.f, xq = 0.f;
  for (int r = 0; r < RITER; ++r){
    int a = warp + 8*r;
    float4 X0 = h4_to_f4(x1b[a*DDW + lane]);
    float4 X1 = h4_to_f4(x1b[a*DDW + lane + 32]);
    float4 xv0 = gelu_pw4(sh_p2, ln4(h4_to_f4(y2b[a*DDW + lane]),      m2, i2));
    float4 xv1 = gelu_pw4(sh_p2, ln4(h4_to_f4(y2b[a*DDW + lane + 32]), m2, i2));
    acc8(xv0, xv1, xs, xq);
    v12b[a*DDW + lane]      = f4_to_h4(f4add(mv4(sh_cwA, X0), mv4(sh_cwB, xv0)));
    v12b[a*DDW + lane + 32] = f4_to_h4(f4add(mv4(sh_cwA, X1), mv4(sh_cwB, xv1)));
    float4 I0 = f4add(f4add(sb[a*DDW + lane],      X0), xv0);
    float4 I1 = f4add(f4add(sb[a*DDW + lane + 32], X1), xv1);
    Taps it = makeTaps(I0, I1, lane);
    float y0[4], y1[4];
    #pragma unroll
    for (int o = 0; o < 4; o++){
      y0[o] = dot4(sh_w3[o], it.m0) + dot4(sh_w3[4+o], I0) + dot4(sh_w3[8+o], it.p0);
      y1[o] = dot4(sh_w3[o], it.m1) + dot4(sh_w3[4+o], I1) + dot4(sh_w3[8+o], it.p1);
    }
    float4 Y0 = make_float4(y0[0], y0[1], y0[2], y0[3]);
    float4 Y1 = make_float4(y1[0], y1[1], y1[2], y1[3]);
    y3b[a*DDW + lane]      = f4_to_h4(Y0);
    y3b[a*DDW + lane + 32] = f4_to_h4(Y1);
    acc8(Y0, Y1, sum, sq);
  }
  blockReduceStore2(sum, sq, &g_p3[blockIdx.x], xs, xq, &g_q2[blockIdx.x]);
}

// ============ K3: x3 from y3h; v = v12 + cwC*x3; zraw; x3 stats ============
__global__ void __launch_bounds__(NTH, 3)
k_passD(const float* __restrict__ d3w2, const float* __restrict__ cw,
        const float* __restrict__ c2w)
{
  __shared__ float2 sh_c2[16*4*32];
  __shared__ float  sh_cwC[16];
  __shared__ float4 sh_p3[4];
  const int b = blockIdx.x >> 4, chk = blockIdx.x & 15, tid = threadIdx.x;
  const int lane = tid & 31, warp = tid >> 5;
  const size_t poff = (size_t)b*NPOS + (size_t)chk*ROWS*DDW;
  const uint2*  y3b  = g_y3h + poff;
  const uint2*  v12b = g_v12h + poff;
  for (int k = tid; k < 2048; k += NTH){
    int l = k & 31, p = (k >> 5) & 3, o = k >> 7;
    sh_c2[k] = make_float2(c2w[o*256 + p*64 + l], c2w[o*256 + p*64 + l + 32]);
  }
  if (tid < 16) sh_cwC[tid] = cw[(tid >> 2)*12 + 8 + (tid & 3)];
  if (tid < 4) sh_p3[tid] = make_float4(d3w2[tid*4+0], d3w2[tid*4+1], d3w2[tid*4+2], d3w2[tid*4+3]);
  float m3, i3; finalizeStats(g_p3, b, INV_N1, m3, i3);
  __syncthreads();

  float xs = 0.f, xq = 0.f;
  float V[RITER][2][4];
  #pragma unroll
  for (int r = 0; r < RITER; ++r){
    int a = warp + 8*r;
    float4 x30 = gelu_pw4(sh_p3, ln4(h4_to_f4(y3b[a*DDW + lane]),      m3, i3));
    float4 x31 = gelu_pw4(sh_p3, ln4(h4_to_f4(y3b[a*DDW + lane + 32]), m3, i3));
    acc8(x30, x31, xs, xq);
    float4 V0 = f4add(h4_to_f4(v12b[a*DDW + lane]),      mv4(sh_cwC, x30));
    float4 V1 = f4add(h4_to_f4(v12b[a*DDW + lane + 32]), mv4(sh_cwC, x31));
    V[r][0][0] = V0.x; V[r][0][1] = V0.y; V[r][0][2] = V0.z; V[r][0][3] = V0.w;
    V[r][1][0] = V1.x; V[r][1][1] = V1.y; V[r][1][2] = V1.z; V[r][1][3] = V1.w;
  }
  #pragma unroll
  for (int o = 0; o < 16; ++o){
    float2 wv[4];
    #pragma unroll
    for (int p = 0; p < 4; p++)
      wv[p] = sh_c2[(o*4 + p)*32 + lane];
    float acc[RITER];
    #pragma unroll
    for (int r = 0; r < RITER; ++r){
      float a0 = 0.f;
      #pragma unroll
      for (int p = 0; p < 4; p++)
        a0 = fmaf(wv[p].x, V[r][0][p], fmaf(wv[p].y, V[r][1][p], a0));
      acc[r] = a0;
    }
    const bool b4 = (lane & 16) != 0, b3 = (lane & 8) != 0;
    float s0 = b4 ? acc[2] : acc[0];
    float s1 = b4 ? acc[3] : acc[1];
    s0 += __shfl_xor_sync(FULLM, b4 ? acc[0] : acc[2], 16);
    s1 += __shfl_xor_sync(FULLM, b4 ? acc[1] : acc[3], 16);
    float sv = b3 ? s1 : s0;
    sv += __shfl_xor_sync(FULLM, b3 ? s0 : s1, 8);
    sv += __shfl_xor_sync(FULLM, sv, 4);
    sv += __shfl_xor_sync(FULLM, sv, 2);
    sv += __shfl_xor_sync(FULLM, sv, 1);
    if ((lane & 7) == 0){
      int r = ((lane >> 4) << 1) | ((lane >> 3) & 1);
      int ag = chk*ROWS + warp + 8*r;
      g_z[((size_t)b*AA + ag)*16 + o] = sv;
    }
  }
  blockReduceStore(xs, xq, &g_q3[blockIdx.x]);
}

// ============ K4: affine-correct zraw -> LN -> +w -> 1x1(17->1) -> LN -> out ============
__global__ void __launch_bounds__(NTH)
k_final(const float* __restrict__ w, const float* __restrict__ cw,
        const float* __restrict__ c2w, const float* __restrict__ c3w,
        float* __restrict__ out)
{
  __shared__ float sh_z[AA*17];
  __shared__ float sh_red[18];
  __shared__ float sh_c3[17];
  __shared__ float sh_K[16];
  const int b = blockIdx.x, tid = threadIdx.x;
  if (tid < 17) sh_c3[tid] = c3w[tid];
  if (tid < 16){
    float csum[4];
    #pragma unroll
    for (int p = 0; p < 4; p++){
      float t = 0.f;
      #pragma unroll
      for (int c = 0; c < 12; c++) t += cw[p*12 + c];
      csum[p] = t;
    }
    float kk = 0.f;
    #pragma unroll
    for (int p = 0; p < 4; p++){
      const float* cb = c2w + tid*256 + p*64;
      float t = 0.f;
      for (int d = 0; d < 64; d++) t += cb[d];
      kk = fmaf(csum[p], t, kk);
    }
    sh_K[tid] = kk;
  }
  float cs = 0.f, cq = 0.f;
  #pragma unroll
  for (int i = 0; i < CH; i++){
    float2 a = __ldg(&g_q1[b*CH + i]);
    float2 c = __ldg(&g_q2[b*CH + i]);
    float2 d = __ldg(&g_q3[b*CH + i]);
    cs += a.x + c.x + d.x; cq += a.y + c.y + d.y;
  }
  float mc = cs*INV_N12;
  float icat = rsqrtf(fmaf(-mc, mc, cq*INV_N12) + EPSF);
  __syncthreads();

  const float4* zsrc = reinterpret_cast<const float4*>(g_z + (size_t)b*AA*16);
  float sz = 0.f, qz = 0.f;
  for (int idx = tid; idx < AA*4; idx += NTH){
    float4 v = zsrc[idx];
    int a = idx >> 2, o4 = (idx & 3)*4;
    v.x = icat*(v.x - mc*sh_K[o4+0]);
    v.y = icat*(v.y - mc*sh_K[o4+1]);
    v.z = icat*(v.z - mc*sh_K[o4+2]);
    v.w = icat*(v.w - mc*sh_K[o4+3]);
    float* dst = sh_z + a*17 + o4;
    dst[0] = v.x; dst[1] = v.y; dst[2] = v.z; dst[3] = v.w;
    sz += v.x+v.y+v.z+v.w;
    qz = fmaf(v.x,v.x, fmaf(v.y,v.y, fmaf(v.z,v.z, fmaf(v.w,v.w, qz))));
  }
  blockReduce2(sz, qz, sh_red);
  const float invN4 = 1.f/(16.f*(float)AA);
  float m4 = sz*invN4;
  float i4 = rsqrtf(fmaf(-m4, m4, qz*invN4) + EPSF);

  float rv[2]; float sr = 0.f, qr = 0.f;
  #pragma unroll
  for (int j = 0; j < 2; j++){
    int a = tid + j*NTH;
    float r = sh_c3[16]*w[(size_t)b*AA + a];
    const float* zr = sh_z + a*17;
    #pragma unroll
    for (int o = 0; o < 16; o++)
      r = fmaf(sh_c3[o], (zr[o] - m4)*i4, r);
    rv[j] = r; sr += r; qr = fmaf(r, r, qr);
  }
  blockReduce2(sr, qr, sh_red);
  float m5 = sr*(1.f/(float)AA);
  float i5 = rsqrtf(fmaf(-m5, m5, qr*(1.f/(float)AA)) + EPSF);
  #pragma unroll
  for (int j = 0; j < 2; j++)
    out[(size_t)b*AA + tid + j*NTH] = (rv[j] - m5)*i5;
}

extern "C" void kernel_launch(void* const* d_in, const int* in_sizes, int n_in,
                              void* d_out, int out_size)
{
  (void)in_sizes; (void)n_in; (void)out_size;
  const float* s    = (const float*)d_in[0];
  const float* w    = (const float*)d_in[1];
  const float* d1w1 = (const float*)d_in[2];
  const float* d1w2 = (const float*)d_in[3];
  const float* d2w1 = (const float*)d_in[4];
  const float* d2w2 = (const float*)d_in[5];
  const float* d3w1 = (const float*)d_in[6];
  const float* d3w2 = (const float*)d_in[7];
  const float* cw   = (const float*)d_in[8];
  const float* c2w  = (const float*)d_in[9];
  const float* c3w  = (const float*)d_in[10];
  float* out = (float*)d_out;

  k_statsA<<<BB*CH, NTH>>>(s, d1w1);
  k_passB <<<BB*CH, NTH>>>(s, d1w2, d2w1);
  k_passC <<<BB*CH, NTH>>>(s, d2w2, d3w1, cw);
  k_passD <<<BB*CH, NTH>>>(d3w2, cw, c2w);
  k_final <<<BB,    NTH>>>(w, cw, c2w, c3w, out);
}

// round 13
// speedup vs baseline: 1.1738x; 1.1603x over previous
#include <cuda_runtime.h>
#include <cuda_fp16.h>
#include <math.h>

#define BB    256
#define AA    512
#define DDW   64
#define NPOS  (AA*DDW)
#define NTH   256
#define CH    8
#define ROWS  (AA/CH)          // 64 rows per chunk
#define EPSF  1e-5f
#define FULLM 0xffffffffu

// fp16 scratch [b][a][d][*4]: y1/y2/y3 pre-LN conv outputs, x1 acts, v12 partial matvec
__device__ uint2  g_y1h[(size_t)BB*NPOS];
__device__ uint2  g_y2h[(size_t)BB*NPOS];
__device__ uint2  g_y3h[(size_t)BB*NPOS];
__device__ uint2  g_x1h[(size_t)BB*NPOS];
__device__ uint2  g_v12h[(size_t)BB*NPOS];
__device__ float  g_z [(size_t)BB*AA*16];
__device__ float2 g_p1[BB*CH], g_p2[BB*CH], g_p3[BB*CH];       // y-stats
__device__ float2 g_q1[BB*CH], g_q2[BB*CH], g_q3[BB*CH];       // x-stats (cat LN)

__device__ __forceinline__ float4 f4add(float4 a, float4 b){
  return make_float4(a.x+b.x, a.y+b.y, a.z+b.z, a.w+b.w);
}
__device__ __forceinline__ float dot4(float4 w, float4 v){
  return fmaf(w.x, v.x, fmaf(w.y, v.y, fmaf(w.z, v.z, w.w*v.w)));
}
__device__ __forceinline__ float geluf(float x){
  return 0.5f * x * (1.f + erff(x * 0.70710678118654752440f));
}
__device__ __forceinline__ uint2 f4_to_h4(const float4& v){
  __half2 a = __floats2half2_rn(v.x, v.y);
  __half2 b = __floats2half2_rn(v.z, v.w);
  uint2 r;
  r.x = *reinterpret_cast<const unsigned int*>(&a);
  r.y = *reinterpret_cast<const unsigned int*>(&b);
  return r;
}
__device__ __forceinline__ float4 h4_to_f4(uint2 u){
  __half2 a = *reinterpret_cast<const __half2*>(&u.x);
  __half2 b = *reinterpret_cast<const __half2*>(&u.y);
  float2 f0 = __half22float2(a);
  float2 f1 = __half22float2(b);
  return make_float4(f0.x, f0.y, f1.x, f1.y);
}
__device__ __forceinline__ float4 ln4(float4 v, float m, float i){
  return make_float4((v.x-m)*i, (v.y-m)*i, (v.z-m)*i, (v.w-m)*i);
}
__device__ __forceinline__ float4 gelu_pw4(const float4* __restrict__ pw, float4 t){
  return make_float4(geluf(dot4(pw[0], t)), geluf(dot4(pw[1], t)),
                     geluf(dot4(pw[2], t)), geluf(dot4(pw[3], t)));
}
__device__ __forceinline__ float4 mv4(const float* __restrict__ W, float4 x){
  float o[4];
  #pragma unroll
  for (int p = 0; p < 4; p++){
    o[p] = fmaf(W[p*4+0], x.x, fmaf(W[p*4+1], x.y,
            fmaf(W[p*4+2], x.z, W[p*4+3]*x.w)));
  }
  return make_float4(o[0], o[1], o[2], o[3]);
}
__device__ __forceinline__ void loadConvW(const float* __restrict__ wp, float4 wk[3][4]){
  #pragma unroll
  for (int o = 0; o < 4; o++)
    #pragma unroll
    for (int k = 0; k < 3; k++)
      wk[k][o] = make_float4(wp[o*12 + 0 + k], wp[o*12 + 3 + k],
                             wp[o*12 + 6 + k], wp[o*12 + 9 + k]);
}
__device__ __forceinline__ float4 shflup2_4(float4 v){
  float4 r;
  r.x = __shfl_up_sync(FULLM, v.x, 2);
  r.y = __shfl_up_sync(FULLM, v.y, 2);
  r.z = __shfl_up_sync(FULLM, v.z, 2);
  r.w = __shfl_up_sync(FULLM, v.w, 2);
  return r;
}
__device__ __forceinline__ float4 shfldn2_4(float4 v){
  float4 r;
  r.x = __shfl_down_sync(FULLM, v.x, 2);
  r.y = __shfl_down_sync(FULLM, v.y, 2);
  r.z = __shfl_down_sync(FULLM, v.z, 2);
  r.w = __shfl_down_sync(FULLM, v.w, 2);
  return r;
}
__device__ __forceinline__ float4 shflsel4(float4 v, int sl){
  float4 r;
  r.x = __shfl_sync(FULLM, v.x, sl);
  r.y = __shfl_sync(FULLM, v.y, sl);
  r.z = __shfl_sync(FULLM, v.z, sl);
  r.w = __shfl_sync(FULLM, v.w, sl);
  return r;
}
struct Taps { float4 m0, p0, m1, p1; };
__device__ __forceinline__ Taps makeTaps(float4 T0, float4 T1, int lane){
  const float4 z4 = make_float4(0.f,0.f,0.f,0.f);
  Taps t;
  t.m0 = shflup2_4(T0);                 if (lane < 2)  t.m0 = z4;
  t.p0 = shflsel4((lane < 2) ? T1 : T0, (lane+2)  & 31);
  t.m1 = shflsel4((lane >= 30) ? T0 : T1, (lane-2) & 31);
  t.p1 = shfldn2_4(T1);                 if (lane >= 30) t.p1 = z4;
  return t;
}

__device__ __forceinline__ void blockReduceStore(float s, float q, float2* dst){
  #pragma unroll
  for (int off = 16; off > 0; off >>= 1){
    s += __shfl_xor_sync(FULLM, s, off);
    q += __shfl_xor_sync(FULLM, q, off);
  }
  __shared__ float red[16];
  int wp = threadIdx.x >> 5, ln = threadIdx.x & 31;
  if (ln == 0){ red[wp] = s; red[8+wp] = q; }
  __syncthreads();
  if (threadIdx.x == 0){
    float ss = 0.f, qq = 0.f;
    #pragma unroll
    for (int i = 0; i < 8; i++){ ss += red[i]; qq += red[8+i]; }
    *dst = make_float2(ss, qq);
  }
}
__device__ __forceinline__ void blockReduceStore2(float s1, float q1, float2* dst1,
                                                  float s2, float q2, float2* dst2){
  #pragma unroll
  for (int off = 16; off > 0; off >>= 1){
    s1 += __shfl_xor_sync(FULLM, s1, off);
    q1 += __shfl_xor_sync(FULLM, q1, off);
    s2 += __shfl_xor_sync(FULLM, s2, off);
    q2 += __shfl_xor_sync(FULLM, q2, off);
  }
  __shared__ float red[32];
  int wp = threadIdx.x >> 5, ln = threadIdx.x & 31;
  if (ln == 0){ red[wp] = s1; red[8+wp] = q1; red[16+wp] = s2; red[24+wp] = q2; }
  __syncthreads();
  if (threadIdx.x == 0){
    float a = 0.f, b = 0.f, c = 0.f, d = 0.f;
    #pragma unroll
    for (int i = 0; i < 8; i++){ a += red[i]; b += red[8+i]; c += red[16+i]; d += red[24+i]; }
    *dst1 = make_float2(a, b);
    *dst2 = make_float2(c, d);
  }
}
__device__ __forceinline__ void finalizeStats(const float2* __restrict__ part, int b,
                                              float invN, float& m, float& inv){
  float s = 0.f, q = 0.f;
  #pragma unroll
  for (int i = 0; i < CH; i++){
    float2 p = __ldg(&part[b*CH + i]);
    s += p.x; q += p.y;
  }
  m = s*invN;
  inv = rsqrtf(fmaf(-m, m, q*invN) + EPSF);
}
__device__ __forceinline__ void blockReduce2(float& s, float& q, volatile float* red){
  #pragma unroll
  for (int off = 16; off > 0; off >>= 1){
    s += __shfl_xor_sync(FULLM, s, off);
    q += __shfl_xor_sync(FULLM, q, off);
  }
  int wp = threadIdx.x >> 5, ln = threadIdx.x & 31;
  __syncthreads();
  if (ln == 0){ red[wp] = s; red[8+wp] = q; }
  __syncthreads();
  if (threadIdx.x == 0){
    float ss = 0.f, qq = 0.f;
    #pragma unroll
    for (int i = 0; i < 8; i++){ ss += red[i]; qq += red[8+i]; }
    red[16] = ss; red[17] = qq;
  }
  __syncthreads();
  s = red[16]; q = red[17];
}
__device__ __forceinline__ void acc8(float4 a, float4 b, float& sum, float& sq){
  sum += a.x+a.y+a.z+a.w + b.x+b.y+b.z+b.w;
  sq = fmaf(a.x,a.x, fmaf(a.y,a.y, fmaf(a.z,a.z, fmaf(a.w,a.w, sq))));
  sq = fmaf(b.x,b.x, fmaf(b.y,b.y, fmaf(b.z,b.z, fmaf(b.w,b.w, sq))));
}

#define INV_N1  (1.f/(4.f*(float)NPOS))
#define INV_N12 (1.f/(12.f*(float)NPOS))

// ============ K0: y1 = conv1(s) -> fp16; stats ============
__global__ void __launch_bounds__(NTH, 4)
k_statsA(const float* __restrict__ s, const float* __restrict__ d1w1)
{
  const int b = blockIdx.x >> 3, chk = blockIdx.x & 7;
  const int lane = threadIdx.x & 31, warp = threadIdx.x >> 5;
  const size_t poff = (size_t)b*NPOS + (size_t)chk*ROWS*DDW;
  const float4* sb = reinterpret_cast<const float4*>(s + poff*4);
  uint2* y1b = g_y1h + poff;
  float4 wk[3][4]; loadConvW(d1w1, wk);
  float sum = 0.f, sq = 0.f;
  for (int r = 0; r < 8; ++r){
    int a = warp + 8*r;
    float4 T0 = sb[a*DDW + lane], T1 = sb[a*DDW + lane + 32];
    Taps tp = makeTaps(T0, T1, lane);
    float y0[4], y1[4];
    #pragma unroll
    for (int o = 0; o < 4; o++){
      y0[o] = dot4(wk[0][o], tp.m0) + dot4(wk[1][o], T0) + dot4(wk[2][o], tp.p0);
      y1[o] = dot4(wk[0][o], tp.m1) + dot4(wk[1][o], T1) + dot4(wk[2][o], tp.p1);
    }
    float4 Y0 = make_float4(y0[0], y0[1], y0[2], y0[3]);
    float4 Y1 = make_float4(y1[0], y1[1], y1[2], y1[3]);
    y1b[a*DDW + lane]      = f4_to_h4(Y0);
    y1b[a*DDW + lane + 32] = f4_to_h4(Y1);
    acc8(Y0, Y1, sum, sq);
  }
  blockReduceStore(sum, sq, &g_p1[blockIdx.x]);
}

// ============ K1: x1 = gelu(pw1(LN(y1h))) -> x1h; y2 = conv2(s+x1); x1 + y2 stats ============
__global__ void __launch_bounds__(NTH, 4)
k_passB(const float* __restrict__ s, const float* __restrict__ d1w2,
        const float* __restrict__ d2w1)
{
  __shared__ float4 sh_w2[12];
  __shared__ float4 sh_p1[4];
  const int b = blockIdx.x >> 3, chk = blockIdx.x & 7, tid = threadIdx.x;
  const int lane = tid & 31, warp = tid >> 5;
  const size_t poff = (size_t)b*NPOS + (size_t)chk*ROWS*DDW;
  const float4* sb  = reinterpret_cast<const float4*>(s + poff*4);
  const uint2*  y1b = g_y1h + poff;
  uint2*        x1b = g_x1h + poff;
  uint2*        y2b = g_y2h + poff;
  if (tid < 12){
    int k = tid >> 2, o = tid & 3;
    sh_w2[tid] = make_float4(d2w1[o*12+k], d2w1[o*12+3+k], d2w1[o*12+6+k], d2w1[o*12+9+k]);
  }
  if (tid < 4) sh_p1[tid] = make_float4(d1w2[tid*4+0], d1w2[tid*4+1], d1w2[tid*4+2], d1w2[tid*4+3]);
  float m1, i1; finalizeStats(g_p1, b, INV_N1, m1, i1);
  __syncthreads();

  float sum = 0.f, sq = 0.f;
  float xs = 0.f, xq = 0.f;
  for (int r = 0; r < 8; ++r){
    int a = warp + 8*r;
    float4 xv0 = gelu_pw4(sh_p1, ln4(h4_to_f4(y1b[a*DDW + lane]),      m1, i1));
    float4 xv1 = gelu_pw4(sh_p1, ln4(h4_to_f4(y1b[a*DDW + lane + 32]), m1, i1));
    x1b[a*DDW + lane]      = f4_to_h4(xv0);
    x1b[a*DDW + lane + 32] = f4_to_h4(xv1);
    acc8(xv0, xv1, xs, xq);
    float4 I0 = f4add(sb[a*DDW + lane],      xv0);
    float4 I1 = f4add(sb[a*DDW + lane + 32], xv1);
    Taps it = makeTaps(I0, I1, lane);
    float y0[4], y1[4];
    #pragma unroll
    for (int o = 0; o < 4; o++){
      y0[o] = dot4(sh_w2[o], it.m0) + dot4(sh_w2[4+o], I0) + dot4(sh_w2[8+o], it.p0);
      y1[o] = dot4(sh_w2[o], it.m1) + dot4(sh_w2[4+o], I1) + dot4(sh_w2[8+o], it.p1);
    }
    float4 Y0 = make_float4(y0[0], y0[1], y0[2], y0[3]);
    float4 Y1 = make_float4(y1[0], y1[1], y1[2], y1[3]);
    y2b[a*DDW + lane]      = f4_to_h4(Y0);
    y2b[a*DDW + lane + 32] = f4_to_h4(Y1);
    acc8(Y0, Y1, sum, sq);
  }
  blockReduceStore2(sum, sq, &g_p2[blockIdx.x], xs, xq, &g_q1[blockIdx.x]);
}

// ============ K2: x2; v12 = cwA*x1 + cwB*x2 -> v12h; y3 = conv3(s+x1+x2); x2 stats ============
__global__ void __launch_bounds__(NTH, 4)
k_passC(const float* __restrict__ s, const float* __restrict__ d2w2,
        const float* __restrict__ d3w1, const float* __restrict__ cw)
{
  __shared__ float4 sh_w3[12];
  __shared__ float4 sh_p2[4];
  __shared__ float  sh_cwA[16];
  __shared__ float  sh_cwB[16];
  const int b = blockIdx.x >> 3, chk = blockIdx.x & 7, tid = threadIdx.x;
  const int lane = tid & 31, warp = tid >> 5;
  const size_t poff = (size_t)b*NPOS + (size_t)chk*ROWS*DDW;
  const float4* sb  = reinterpret_cast<const float4*>(s + poff*4);
  const uint2*  x1b = g_x1h + poff;
  const uint2*  y2b = g_y2h + poff;
  uint2*        v12b = g_v12h + poff;
  uint2*        y3b = g_y3h + poff;
  if (tid < 12){
    int k = tid >> 2, o = tid & 3;
    sh_w3[tid] = make_float4(d3w1[o*12+k], d3w1[o*12+3+k], d3w1[o*12+6+k], d3w1[o*12+9+k]);
  }
  if (tid < 4) sh_p2[tid] = make_float4(d2w2[tid*4+0], d2w2[tid*4+1], d2w2[tid*4+2], d2w2[tid*4+3]);
  if (tid < 16){
    sh_cwA[tid] = cw[(tid >> 2)*12 + (tid & 3)];
    sh_cwB[tid] = cw[(tid >> 2)*12 + 4 + (tid & 3)];
  }
  float m2, i2; finalizeStats(g_p2, b, INV_N1, m2, i2);
  __syncthreads();

  float sum = 0.f, sq = 0.f;
  float xs = 0.f, xq = 0.f;
  for (int r = 0; r < 8; ++r){
    int a = warp + 8*r;
    float4 X0 = h4_to_f4(x1b[a*DDW + lane]);
    float4 X1 = h4_to_f4(x1b[a*DDW + lane + 32]);
    float4 xv0 = gelu_pw4(sh_p2, ln4(h4_to_f4(y2b[a*DDW + lane]),      m2, i2));
    float4 xv1 = gelu_pw4(sh_p2, ln4(h4_to_f4(y2b[a*DDW + lane + 32]), m2, i2));
    acc8(xv0, xv1, xs, xq);
    v12b[a*DDW + lane]      = f4_to_h4(f4add(mv4(sh_cwA, X0), mv4(sh_cwB, xv0)));
    v12b[a*DDW + lane + 32] = f4_to_h4(f4add(mv4(sh_cwA, X1), mv4(sh_cwB, xv1)));
    float4 I0 = f4add(f4add(sb[a*DDW + lane],      X0), xv0);
    float4 I1 = f4add(f4add(sb[a*DDW + lane + 32], X1), xv1);
    Taps it = makeTaps(I0, I1, lane);
    float y0[4], y1[4];
    #pragma unroll
    for (int o = 0; o < 4; o++){
      y0[o] = dot4(sh_w3[o], it.m0) + dot4(sh_w3[4+o], I0) + dot4(sh_w3[8+o], it.p0);
      y1[o] = dot4(sh_w3[o], it.m1) + dot4(sh_w3[4+o], I1) + dot4(sh_w3[8+o], it.p1);
    }
    float4 Y0 = make_float4(y0[0], y0[1], y0[2], y0[3]);
    float4 Y1 = make_float4(y1[0], y1[1], y1[2], y1[3]);
    y3b[a*DDW + lane]      = f4_to_h4(Y0);
    y3b[a*DDW + lane + 32] = f4_to_h4(Y1);
    acc8(Y0, Y1, sum, sq);
  }
  blockReduceStore2(sum, sq, &g_p3[blockIdx.x], xs, xq, &g_q2[blockIdx.x]);
}

// ============ K3: x3 from y3h; v = v12 + cwC*x3; zraw; x3 stats ============
__global__ void __launch_bounds__(NTH, 4)
k_passD(const float* __restrict__ d3w2, const float* __restrict__ cw,
        const float* __restrict__ c2w)
{
  __shared__ float2 sh_c2[16*4*32];
  __shared__ float  sh_cwC[16];
  __shared__ float4 sh_p3[4];
  const int b = blockIdx.x >> 3, chk = blockIdx.x & 7, tid = threadIdx.x;
  const int lane = tid & 31, warp = tid >> 5;
  const size_t poff = (size_t)b*NPOS + (size_t)chk*ROWS*DDW;
  const uint2*  y3b  = g_y3h + poff;
  const uint2*  v12b = g_v12h + poff;
  for (int k = tid; k < 2048; k += NTH){
    int l = k & 31, p = (k >> 5) & 3, o = k >> 7;
    sh_c2[k] = make_float2(c2w[o*256 + p*64 + l], c2w[o*256 + p*64 + l + 32]);
  }
  if (tid < 16) sh_cwC[tid] = cw[(tid >> 2)*12 + 8 + (tid & 3)];
  if (tid < 4) sh_p3[tid] = make_float4(d3w2[tid*4+0], d3w2[tid*4+1], d3w2[tid*4+2], d3w2[tid*4+3]);
  float m3, i3; finalizeStats(g_p3, b, INV_N1, m3, i3);
  __syncthreads();

  float xs = 0.f, xq = 0.f;
  for (int g = 0; g < 2; ++g){
    float V[4][2][4];
    #pragma unroll
    for (int r = 0; r < 4; ++r){
      int a = warp + 8*(4*g + r);
      float4 x30 = gelu_pw4(sh_p3, ln4(h4_to_f4(y3b[a*DDW + lane]),      m3, i3));
      float4 x31 = gelu_pw4(sh_p3, ln4(h4_to_f4(y3b[a*DDW + lane + 32]), m3, i3));
      acc8(x30, x31, xs, xq);
      float4 V0 = f4add(h4_to_f4(v12b[a*DDW + lane]),      mv4(sh_cwC, x30));
      float4 V1 = f4add(h4_to_f4(v12b[a*DDW + lane + 32]), mv4(sh_cwC, x31));
      V[r][0][0] = V0.x; V[r][0][1] = V0.y; V[r][0][2] = V0.z; V[r][0][3] = V0.w;
      V[r][1][0] = V1.x; V[r][1][1] = V1.y; V[r][1][2] = V1.z; V[r][1][3] = V1.w;
    }
    #pragma unroll
    for (int o = 0; o < 16; ++o){
      float2 wv[4];
      #pragma unroll
      for (int p = 0; p < 4; p++)
        wv[p] = sh_c2[(o*4 + p)*32 + lane];
      float acc[4];
      #pragma unroll
      for (int r = 0; r < 4; ++r){
        float a0 = 0.f;
        #pragma unroll
        for (int p = 0; p < 4; p++)
          a0 = fmaf(wv[p].x, V[r][0][p], fmaf(wv[p].y, V[r][1][p], a0));
        acc[r] = a0;
      }
      const bool b4 = (lane & 16) != 0, b3 = (lane & 8) != 0;
      float s0 = b4 ? acc[2] : acc[0];
      float s1 = b4 ? acc[3] : acc[1];
      s0 += __shfl_xor_sync(FULLM, b4 ? acc[0] : acc[2], 16);
      s1 += __shfl_xor_sync(FULLM, b4 ? acc[1] : acc[3], 16);
      float sv = b3 ? s1 : s0;
      sv += __shfl_xor_sync(FULLM, b3 ? s0 : s1, 8);
      sv += __shfl_xor_sync(FULLM, sv, 4);
      sv += __shfl_xor_sync(FULLM, sv, 2);
      sv += __shfl_xor_sync(FULLM, sv, 1);
      if ((lane & 7) == 0){
        int r = ((lane >> 4) << 1) | ((lane >> 3) & 1);
        int ag = chk*ROWS + warp + 8*(4*g + r);
        g_z[((size_t)b*AA + ag)*16 + o] = sv;
      }
    }
  }
  blockReduceStore(xs, xq, &g_q3[blockIdx.x]);
}

// ============ K4: affine-correct zraw -> LN -> +w -> 1x1(17->1) -> LN -> out ============
__global__ void __launch_bounds__(NTH)
k_final(const float* __restrict__ w, const float* __restrict__ cw,
        const float* __restrict__ c2w, const float* __restrict__ c3w,
        float* __restrict__ out)
{
  __shared__ float sh_z[AA*17];
  __shared__ float sh_red[18];
  __shared__ float sh_c3[17];
  __shared__ float sh_K[16];
  const int b = blockIdx.x, tid = threadIdx.x;
  if (tid < 17) sh_c3[tid] = c3w[tid];
  if (tid < 16){
    float csum[4];
    #pragma unroll
    for (int p = 0; p < 4; p++){
      float t = 0.f;
      #pragma unroll
      for (int c = 0; c < 12; c++) t += cw[p*12 + c];
      csum[p] = t;
    }
    float kk = 0.f;
    #pragma unroll
    for (int p = 0; p < 4; p++){
      const float* cb = c2w + tid*256 + p*64;
      float t = 0.f;
      for (int d = 0; d < 64; d++) t += cb[d];
      kk = fmaf(csum[p], t, kk);
    }
    sh_K[tid] = kk;
  }
  float cs = 0.f, cq = 0.f;
  #pragma unroll
  for (int i = 0; i < CH; i++){
    float2 a = __ldg(&g_q1[b*CH + i]);
    float2 c = __ldg(&g_q2[b*CH + i]);
    float2 d = __ldg(&g_q3[b*CH + i]);
    cs += a.x + c.x + d.x; cq += a.y + c.y + d.y;
  }
  float mc = cs*INV_N12;
  float icat = rsqrtf(fmaf(-mc, mc, cq*INV_N12) + EPSF);
  __syncthreads();

  const float4* zsrc = reinterpret_cast<const float4*>(g_z + (size_t)b*AA*16);
  float sz = 0.f, qz = 0.f;
  for (int idx = tid; idx < AA*4; idx += NTH){
    float4 v = zsrc[idx];
    int a = idx >> 2, o4 = (idx & 3)*4;
    v.x = icat*(v.x - mc*sh_K[o4+0]);
    v.y = icat*(v.y - mc*sh_K[o4+1]);
    v.z = icat*(v.z - mc*sh_K[o4+2]);
    v.w = icat*(v.w - mc*sh_K[o4+3]);
    float* dst = sh_z + a*17 + o4;
    dst[0] = v.x; dst[1] = v.y; dst[2] = v.z; dst[3] = v.w;
    sz += v.x+v.y+v.z+v.w;
    qz = fmaf(v.x,v.x, fmaf(v.y,v.y, fmaf(v.z,v.z, fmaf(v.w,v.w, qz))));
  }
  blockReduce2(sz, qz, sh_red);
  const float invN4 = 1.f/(16.f*(float)AA);
  float m4 = sz*invN4;
  float i4 = rsqrtf(fmaf(-m4, m4, qz*invN4) + EPSF);

  float rv[2]; float sr = 0.f, qr = 0.f;
  #pragma unroll
  for (int j = 0; j < 2; j++){
    int a = tid + j*NTH;
    float r = sh_c3[16]*w[(size_t)b*AA + a];
    const float* zr = sh_z + a*17;
    #pragma unroll
    for (int o = 0; o < 16; o++)
      r = fmaf(sh_c3[o], (zr[o] - m4)*i4, r);
    rv[j] = r; sr += r; qr = fmaf(r, r, qr);
  }
  blockReduce2(sr, qr, sh_red);
  float m5 = sr*(1.f/(float)AA);
  float i5 = rsqrtf(fmaf(-m5, m5, qr*(1.f/(float)AA)) + EPSF);
  #pragma unroll
  for (int j = 0; j < 2; j++)
    out[(size_t)b*AA + tid + j*NTH] = (rv[j] - m5)*i5;
}

extern "C" void kernel_launch(void* const* d_in, const int* in_sizes, int n_in,
                              void* d_out, int out_size)
{
  (void)in_sizes; (void)n_in; (void)out_size;
  const float* s    = (const float*)d_in[0];
  const float* w    = (const float*)d_in[1];
  const float* d1w1 = (const float*)d_in[2];
  const float* d1w2 = (const float*)d_in[3];
  const float* d2w1 = (const float*)d_in[4];
  const float* d2w2 = (const float*)d_in[5];
  const float* d3w1 = (const float*)d_in[6];
  const float* d3w2 = (const float*)d_in[7];
  const float* cw   = (const float*)d_in[8];
  const float* c2w  = (const float*)d_in[9];
  const float* c3w  = (const float*)d_in[10];
  float* out = (float*)d_out;

  k_statsA<<<BB*CH, NTH>>>(s, d1w1);
  k_passB <<<BB*CH, NTH>>>(s, d1w2, d2w1);
  k_passC <<<BB*CH, NTH>>>(s, d2w2, d3w1, cw);
  k_passD <<<BB*CH, NTH>>>(d3w2, cw, c2w);
  k_final <<<BB,    NTH>>>(w, cw, c2w, c3w, out);
}

// round 14
// speedup vs baseline: 1.2206x; 1.0399x over previous
#include <cuda_runtime.h>
#include <cuda_fp16.h>
#include <math.h>

#define BB    256
#define AA    512
#define DDW   64
#define NPOS  (AA*DDW)
#define NTH   256
#define CH    8
#define ROWS  (AA/CH)          // 64 rows per chunk
#define EPSF  1e-5f
#define FULLM 0xffffffffu

// fp16 scratch [b][a][d][*4]: y1/y2/y3 pre-LN conv outputs, x1 acts, v12 partial matvec
__device__ uint2  g_y1h[(size_t)BB*NPOS];
__device__ uint2  g_y2h[(size_t)BB*NPOS];
__device__ uint2  g_y3h[(size_t)BB*NPOS];
__device__ uint2  g_x1h[(size_t)BB*NPOS];
__device__ uint2  g_v12h[(size_t)BB*NPOS];
__device__ float  g_z [(size_t)BB*AA*16];
__device__ float2 g_p1[BB*CH], g_p2[BB*CH], g_p3[BB*CH];       // y-stats
__device__ float2 g_q1[BB*CH], g_q2[BB*CH], g_q3[BB*CH];       // x-stats (cat LN)

__device__ __forceinline__ float4 f4add(float4 a, float4 b){
  return make_float4(a.x+b.x, a.y+b.y, a.z+b.z, a.w+b.w);
}
__device__ __forceinline__ float dot4(float4 w, float4 v){
  return fmaf(w.x, v.x, fmaf(w.y, v.y, fmaf(w.z, v.z, w.w*v.w)));
}
__device__ __forceinline__ float geluf(float x){
  return 0.5f * x * (1.f + erff(x * 0.70710678118654752440f));
}
__device__ __forceinline__ uint2 f4_to_h4(const float4& v){
  __half2 a = __floats2half2_rn(v.x, v.y);
  __half2 b = __floats2half2_rn(v.z, v.w);
  uint2 r;
  r.x = *reinterpret_cast<const unsigned int*>(&a);
  r.y = *reinterpret_cast<const unsigned int*>(&b);
  return r;
}
__device__ __forceinline__ float4 h4_to_f4(uint2 u){
  __half2 a = *reinterpret_cast<const __half2*>(&u.x);
  __half2 b = *reinterpret_cast<const __half2*>(&u.y);
  float2 f0 = __half22float2(a);
  float2 f1 = __half22float2(b);
  return make_float4(f0.x, f0.y, f1.x, f1.y);
}
__device__ __forceinline__ float4 ln4(float4 v, float m, float i){
  return make_float4((v.x-m)*i, (v.y-m)*i, (v.z-m)*i, (v.w-m)*i);
}
__device__ __forceinline__ float4 gelu_pw4(const float4* __restrict__ pw, float4 t){
  return make_float4(geluf(dot4(pw[0], t)), geluf(dot4(pw[1], t)),
                     geluf(dot4(pw[2], t)), geluf(dot4(pw[3], t)));
}
__device__ __forceinline__ float4 mv4(const float* __restrict__ W, float4 x){
  float o[4];
  #pragma unroll
  for (int p = 0; p < 4; p++){
    o[p] = fmaf(W[p*4+0], x.x, fmaf(W[p*4+1], x.y,
            fmaf(W[p*4+2], x.z, W[p*4+3]*x.w)));
  }
  return make_float4(o[0], o[1], o[2], o[3]);
}
__device__ __forceinline__ void loadConvW(const float* __restrict__ wp, float4 wk[3][4]){
  #pragma unroll
  for (int o = 0; o < 4; o++)
    #pragma unroll
    for (int k = 0; k < 3; k++)
      wk[k][o] = make_float4(wp[o*12 + 0 + k], wp[o*12 + 3 + k],
                             wp[o*12 + 6 + k], wp[o*12 + 9 + k]);
}
__device__ __forceinline__ float4 shflup2_4(float4 v){
  float4 r;
  r.x = __shfl_up_sync(FULLM, v.x, 2);
  r.y = __shfl_up_sync(FULLM, v.y, 2);
  r.z = __shfl_up_sync(FULLM, v.z, 2);
  r.w = __shfl_up_sync(FULLM, v.w, 2);
  return r;
}
__device__ __forceinline__ float4 shfldn2_4(float4 v){
  float4 r;
  r.x = __shfl_down_sync(FULLM, v.x, 2);
  r.y = __shfl_down_sync(FULLM, v.y, 2);
  r.z = __shfl_down_sync(FULLM, v.z, 2);
  r.w = __shfl_down_sync(FULLM, v.w, 2);
  return r;
}
__device__ __forceinline__ float4 shflsel4(float4 v, int sl){
  float4 r;
  r.x = __shfl_sync(FULLM, v.x, sl);
  r.y = __shfl_sync(FULLM, v.y, sl);
  r.z = __shfl_sync(FULLM, v.z, sl);
  r.w = __shfl_sync(FULLM, v.w, sl);
  return r;
}
struct Taps { float4 m0, p0, m1, p1; };
__device__ __forceinline__ Taps makeTaps(float4 T0, float4 T1, int lane){
  const float4 z4 = make_float4(0.f,0.f,0.f,0.f);
  Taps t;
  t.m0 = shflup2_4(T0);                 if (lane < 2)  t.m0 = z4;
  t.p0 = shflsel4((lane < 2) ? T1 : T0, (lane+2)  & 31);
  t.m1 = shflsel4((lane >= 30) ? T0 : T1, (lane-2) & 31);
  t.p1 = shfldn2_4(T1);                 if (lane >= 30) t.p1 = z4;
  return t;
}

__device__ __forceinline__ void blockReduceStore(float s, float q, float2* dst){
  #pragma unroll
  for (int off = 16; off > 0; off >>= 1){
    s += __shfl_xor_sync(FULLM, s, off);
    q += __shfl_xor_sync(FULLM, q, off);
  }
  __shared__ float red[16];
  int wp = threadIdx.x >> 5, ln = threadIdx.x & 31;
  if (ln == 0){ red[wp] = s; red[8+wp] = q; }
  __syncthreads();
  if (threadIdx.x == 0){
    float ss = 0.f, qq = 0.f;
    #pragma unroll
    for (int i = 0; i < 8; i++){ ss += red[i]; qq += red[8+i]; }
    *dst = make_float2(ss, qq);
  }
}
__device__ __forceinline__ void blockReduceStore2(float s1, float q1, float2* dst1,
                                                  float s2, float q2, float2* dst2){
  #pragma unroll
  for (int off = 16; off > 0; off >>= 1){
    s1 += __shfl_xor_sync(FULLM, s1, off);
    q1 += __shfl_xor_sync(FULLM, q1, off);
    s2 += __shfl_xor_sync(FULLM, s2, off);
    q2 += __shfl_xor_sync(FULLM, q2, off);
  }
  __shared__ float red[32];
  int wp = threadIdx.x >> 5, ln = threadIdx.x & 31;
  if (ln == 0){ red[wp] = s1; red[8+wp] = q1; red[16+wp] = s2; red[24+wp] = q2; }
  __syncthreads();
  if (threadIdx.x == 0){
    float a = 0.f, b = 0.f, c = 0.f, d = 0.f;
    #pragma unroll
    for (int i = 0; i < 8; i++){ a += red[i]; b += red[8+i]; c += red[16+i]; d += red[24+i]; }
    *dst1 = make_float2(a, b);
    *dst2 = make_float2(c, d);
  }
}
__device__ __forceinline__ void finalizeStats(const float2* __restrict__ part, int b,
                                              float invN, float& m, float& inv){
  float s = 0.f, q = 0.f;
  #pragma unroll
  for (int i = 0; i < CH; i++){
    float2 p = __ldg(&part[b*CH + i]);
    s += p.x; q += p.y;
  }
  m = s*invN;
  inv = rsqrtf(fmaf(-m, m, q*invN) + EPSF);
}
__device__ __forceinline__ void blockReduce2(float& s, float& q, volatile float* red){
  #pragma unroll
  for (int off = 16; off > 0; off >>= 1){
    s += __shfl_xor_sync(FULLM, s, off);
    q += __shfl_xor_sync(FULLM, q, off);
  }
  int wp = threadIdx.x >> 5, ln = threadIdx.x & 31;
  __syncthreads();
  if (ln == 0){ red[wp] = s; red[8+wp] = q; }
  __syncthreads();
  if (threadIdx.x == 0){
    float ss = 0.f, qq = 0.f;
    #pragma unroll
    for (int i = 0; i < 8; i++){ ss += red[i]; qq += red[8+i]; }
    red[16] = ss; red[17] = qq;
  }
  __syncthreads();
  s = red[16]; q = red[17];
}
__device__ __forceinline__ void acc8(float4 a, float4 b, float& sum, float& sq){
  sum += a.x+a.y+a.z+a.w + b.x+b.y+b.z+b.w;
  sq = fmaf(a.x,a.x, fmaf(a.y,a.y, fmaf(a.z,a.z, fmaf(a.w,a.w, sq))));
  sq = fmaf(b.x,b.x, fmaf(b.y,b.y, fmaf(b.z,b.z, fmaf(b.w,b.w, sq))));
}

#define INV_N1  (1.f/(4.f*(float)NPOS))
#define INV_N12 (1.f/(12.f*(float)NPOS))

// ============ K0: y1 = conv1(s) -> fp16; stats ============
__global__ void __launch_bounds__(NTH, 4)
k_statsA(const float* __restrict__ s, const float* __restrict__ d1w1)
{
  const int b = blockIdx.x >> 3, chk = blockIdx.x & 7;
  const int lane = threadIdx.x & 31, warp = threadIdx.x >> 5;
  const size_t poff = (size_t)b*NPOS + (size_t)chk*ROWS*DDW;
  const float4* sb = reinterpret_cast<const float4*>(s + poff*4);
  uint2* y1b = g_y1h + poff;
  float4 wk[3][4]; loadConvW(d1w1, wk);
  float sum = 0.f, sq = 0.f;
  for (int r = 0; r < 8; ++r){
    int a = warp + 8*r;
    float4 T0 = sb[a*DDW + lane], T1 = sb[a*DDW + lane + 32];
    Taps tp = makeTaps(T0, T1, lane);
    float y0[4], y1[4];
    #pragma unroll
    for (int o = 0; o < 4; o++){
      y0[o] = dot4(wk[0][o], tp.m0) + dot4(wk[1][o], T0) + dot4(wk[2][o], tp.p0);
      y1[o] = dot4(wk[0][o], tp.m1) + dot4(wk[1][o], T1) + dot4(wk[2][o], tp.p1);
    }
    float4 Y0 = make_float4(y0[0], y0[1], y0[2], y0[3]);
    float4 Y1 = make_float4(y1[0], y1[1], y1[2], y1[3]);
    y1b[a*DDW + lane]      = f4_to_h4(Y0);
    y1b[a*DDW + lane + 32] = f4_to_h4(Y1);
    acc8(Y0, Y1, sum, sq);
  }
  blockReduceStore(sum, sq, &g_p1[blockIdx.x]);
}

// ============ K1: x1 = gelu(pw1(LN(y1h))) -> x1h; y2 = conv2(s+x1); x1 + y2 stats ============
__global__ void __launch_bounds__(NTH, 4)
k_passB(const float* __restrict__ s, const float* __restrict__ d1w2,
        const float* __restrict__ d2w1)
{
  __shared__ float4 sh_w2[12];
  __shared__ float4 sh_p1[4];
  const int b = blockIdx.x >> 3, chk = blockIdx.x & 7, tid = threadIdx.x;
  const int lane = tid & 31, warp = tid >> 5;
  const size_t poff = (size_t)b*NPOS + (size_t)chk*ROWS*DDW;
  const float4* sb  = reinterpret_cast<const float4*>(s + poff*4);
  const uint2*  y1b = g_y1h + poff;
  uint2*        x1b = g_x1h + poff;
  uint2*        y2b = g_y2h + poff;
  if (tid < 12){
    int k = tid >> 2, o = tid & 3;
    sh_w2[tid] = make_float4(d2w1[o*12+k], d2w1[o*12+3+k], d2w1[o*12+6+k], d2w1[o*12+9+k]);
  }
  if (tid < 4) sh_p1[tid] = make_float4(d1w2[tid*4+0], d1w2[tid*4+1], d1w2[tid*4+2], d1w2[tid*4+3]);
  float m1, i1; finalizeStats(g_p1, b, INV_N1, m1, i1);
  __syncthreads();

  float sum = 0.f, sq = 0.f;
  float xs = 0.f, xq = 0.f;
  for (int r = 0; r < 8; ++r){
    int a = warp + 8*r;
    float4 xv0 = gelu_pw4(sh_p1, ln4(h4_to_f4(y1b[a*DDW + lane]),      m1, i1));
    float4 xv1 = gelu_pw4(sh_p1, ln4(h4_to_f4(y1b[a*DDW + lane + 32]), m1, i1));
    x1b[a*DDW + lane]      = f4_to_h4(xv0);
    x1b[a*DDW + lane + 32] = f4_to_h4(xv1);
    acc8(xv0, xv1, xs, xq);
    float4 I0 = f4add(sb[a*DDW + lane],      xv0);
    float4 I1 = f4add(sb[a*DDW + lane + 32], xv1);
    Taps it = makeTaps(I0, I1, lane);
    float y0[4], y1[4];
    #pragma unroll
    for (int o = 0; o < 4; o++){
      y0[o] = dot4(sh_w2[o], it.m0) + dot4(sh_w2[4+o], I0) + dot4(sh_w2[8+o], it.p0);
      y1[o] = dot4(sh_w2[o], it.m1) + dot4(sh_w2[4+o], I1) + dot4(sh_w2[8+o], it.p1);
    }
    float4 Y0 = make_float4(y0[0], y0[1], y0[2], y0[3]);
    float4 Y1 = make_float4(y1[0], y1[1], y1[2], y1[3]);
    y2b[a*DDW + lane]      = f4_to_h4(Y0);
    y2b[a*DDW + lane + 32] = f4_to_h4(Y1);
    acc8(Y0, Y1, sum, sq);
  }
  blockReduceStore2(sum, sq, &g_p2[blockIdx.x], xs, xq, &g_q1[blockIdx.x]);
}

// ============ K2: x2; v12 = cwA*x1 + cwB*x2 -> v12h; y3 = conv3(s+x1+x2); x2 stats ============
__global__ void __launch_bounds__(NTH, 4)
k_passC(const float* __restrict__ s, const float* __restrict__ d2w2,
        const float* __restrict__ d3w1, const float* __restrict__ cw)
{
  __shared__ float4 sh_w3[12];
  __shared__ float4 sh_p2[4];
  __shared__ float  sh_cwA[16];
  __shared__ float  sh_cwB[16];
  const int b = blockIdx.x >> 3, chk = blockIdx.x & 7, tid = threadIdx.x;
  const int lane = tid & 31, warp = tid >> 5;
  const size_t poff = (size_t)b*NPOS + (size_t)chk*ROWS*DDW;
  const float4* sb  = reinterpret_cast<const float4*>(s + poff*4);
  const uint2*  x1b = g_x1h + poff;
  const uint2*  y2b = g_y2h + poff;
  uint2*        v12b = g_v12h + poff;
  uint2*        y3b = g_y3h + poff;
  if (tid < 12){
    int k = tid >> 2, o = tid & 3;
    sh_w3[tid] = make_float4(d3w1[o*12+k], d3w1[o*12+3+k], d3w1[o*12+6+k], d3w1[o*12+9+k]);
  }
  if (tid < 4) sh_p2[tid] = make_float4(d2w2[tid*4+0], d2w2[tid*4+1], d2w2[tid*4+2], d2w2[tid*4+3]);
  if (tid < 16){
    sh_cwA[tid] = cw[(tid >> 2)*12 + (tid & 3)];
    sh_cwB[tid] = cw[(tid >> 2)*12 + 4 + (tid & 3)];
  }
  float m2, i2; finalizeStats(g_p2, b, INV_N1, m2, i2);
  __syncthreads();

  float sum = 0.f, sq = 0.f;
  float xs = 0.f, xq = 0.f;
  for (int r = 0; r < 8; ++r){
    int a = warp + 8*r;
    float4 X0 = h4_to_f4(x1b[a*DDW + lane]);
    float4 X1 = h4_to_f4(x1b[a*DDW + lane + 32]);
    float4 xv0 = gelu_pw4(sh_p2, ln4(h4_to_f4(y2b[a*DDW + lane]),      m2, i2));
    float4 xv1 = gelu_pw4(sh_p2, ln4(h4_to_f4(y2b[a*DDW + lane + 32]), m2, i2));
    acc8(xv0, xv1, xs, xq);
    v12b[a*DDW + lane]      = f4_to_h4(f4add(mv4(sh_cwA, X0), mv4(sh_cwB, xv0)));
    v12b[a*DDW + lane + 32] = f4_to_h4(f4add(mv4(sh_cwA, X1), mv4(sh_cwB, xv1)));
    float4 I0 = f4add(f4add(sb[a*DDW + lane],      X0), xv0);
    float4 I1 = f4add(f4add(sb[a*DDW + lane + 32], X1), xv1);
    Taps it = makeTaps(I0, I1, lane);
    float y0[4], y1[4];
    #pragma unroll
    for (int o = 0; o < 4; o++){
      y0[o] = dot4(sh_w3[o], it.m0) + dot4(sh_w3[4+o], I0) + dot4(sh_w3[8+o], it.p0);
      y1[o] = dot4(sh_w3[o], it.m1) + dot4(sh_w3[4+o], I1) + dot4(sh_w3[8+o], it.p1);
    }
    float4 Y0 = make_float4(y0[0], y0[1], y0[2], y0[3]);
    float4 Y1 = make_float4(y1[0], y1[1], y1[2], y1[3]);
    y3b[a*DDW + lane]      = f4_to_h4(Y0);
    y3b[a*DDW + lane + 32] = f4_to_h4(Y1);
    acc8(Y0, Y1, sum, sq);
  }
  blockReduceStore2(sum, sq, &g_p3[blockIdx.x], xs, xq, &g_q2[blockIdx.x]);
}

// ============ K3: x3 from y3h; v = v12 + cwC*x3; zraw; x3 stats ============
__global__ void __launch_bounds__(NTH, 3)
k_passD(const float* __restrict__ d3w2, const float* __restrict__ cw,
        const float* __restrict__ c2w)
{
  __shared__ float2 sh_c2[16*4*32];
  __shared__ float  sh_cwC[16];
  __shared__ float4 sh_p3[4];
  const int b = blockIdx.x >> 3, chk = blockIdx.x & 7, tid = threadIdx.x;
  const int lane = tid & 31, warp = tid >> 5;
  const size_t poff = (size_t)b*NPOS + (size_t)chk*ROWS*DDW;
  const uint2*  y3b  = g_y3h + poff;
  const uint2*  v12b = g_v12h + poff;
  for (int k = tid; k < 2048; k += NTH){
    int l = k & 31, p = (k >> 5) & 3, o = k >> 7;
    sh_c2[k] = make_float2(c2w[o*256 + p*64 + l], c2w[o*256 + p*64 + l + 32]);
  }
  if (tid < 16) sh_cwC[tid] = cw[(tid >> 2)*12 + 8 + (tid & 3)];
  if (tid < 4) sh_p3[tid] = make_float4(d3w2[tid*4+0], d3w2[tid*4+1], d3w2[tid*4+2], d3w2[tid*4+3]);
  float m3, i3; finalizeStats(g_p3, b, INV_N1, m3, i3);
  __syncthreads();

  float xs = 0.f, xq = 0.f;
  for (int g = 0; g < 2; ++g){
    float V[4][2][4];
    #pragma unroll
    for (int r = 0; r < 4; ++r){
      int a = warp + 8*(4*g + r);
      float4 x30 = gelu_pw4(sh_p3, ln4(h4_to_f4(y3b[a*DDW + lane]),      m3, i3));
      float4 x31 = gelu_pw4(sh_p3, ln4(h4_to_f4(y3b[a*DDW + lane + 32]), m3, i3));
      acc8(x30, x31, xs, xq);
      float4 V0 = f4add(h4_to_f4(v12b[a*DDW + lane]),      mv4(sh_cwC, x30));
      float4 V1 = f4add(h4_to_f4(v12b[a*DDW + lane + 32]), mv4(sh_cwC, x31));
      V[r][0][0] = V0.x; V[r][0][1] = V0.y; V[r][0][2] = V0.z; V[r][0][3] = V0.w;
      V[r][1][0] = V1.x; V[r][1][1] = V1.y; V[r][1][2] = V1.z; V[r][1][3] = V1.w;
    }
    #pragma unroll
    for (int o = 0; o < 16; ++o){
      float2 wv[4];
      #pragma unroll
      for (int p = 0; p < 4; p++)
        wv[p] = sh_c2[(o*4 + p)*32 + lane];
      float acc[4];
      #pragma unroll
      for (int r = 0; r < 4; ++r){
        float a0 = 0.f;
        #pragma unroll
        for (int p = 0; p < 4; p++)
          a0 = fmaf(wv[p].x, V[r][0][p], fmaf(wv[p].y, V[r][1][p], a0));
        acc[r] = a0;
      }
      const bool b4 = (lane & 16) != 0, b3 = (lane & 8) != 0;
      float s0 = b4 ? acc[2] : acc[0];
      float s1 = b4 ? acc[3] : acc[1];
      s0 += __shfl_xor_sync(FULLM, b4 ? acc[0] : acc[2], 16);
      s1 += __shfl_xor_sync(FULLM, b4 ? acc[1] : acc[3], 16);
      float sv = b3 ? s1 : s0;
      sv += __shfl_xor_sync(FULLM, b3 ? s0 : s1, 8);
      sv += __shfl_xor_sync(FULLM, sv, 4);
      sv += __shfl_xor_sync(FULLM, sv, 2);
      sv += __shfl_xor_sync(FULLM, sv, 1);
      if ((lane & 7) == 0){
        int r = ((lane >> 4) << 1) | ((lane >> 3) & 1);
        int ag = chk*ROWS + warp + 8*(4*g + r);
        g_z[((size_t)b*AA + ag)*16 + o] = sv;
      }
    }
  }
  blockReduceStore(xs, xq, &g_q3[blockIdx.x]);
}

// ============ K4: affine-correct zraw -> LN -> +w -> 1x1(17->1) -> LN -> out ============
__global__ void __launch_bounds__(NTH)
k_final(const float* __restrict__ w, const float* __restrict__ cw,
        const float* __restrict__ c2w, const float* __restrict__ c3w,
        float* __restrict__ out)
{
  __shared__ float sh_z[AA*17];
  __shared__ float sh_red[18];
  __shared__ float sh_c3[17];
  __shared__ float sh_K[16];
  const int b = blockIdx.x, tid = threadIdx.x;
  if (tid < 17) sh_c3[tid] = c3w[tid];
  if (tid < 16){
    float csum[4];
    #pragma unroll
    for (int p = 0; p < 4; p++){
      float t = 0.f;
      #pragma unroll
      for (int c = 0; c < 12; c++) t += cw[p*12 + c];
      csum[p] = t;
    }
    float kk = 0.f;
    #pragma unroll
    for (int p = 0; p < 4; p++){
      const float* cb = c2w + tid*256 + p*64;
      float t = 0.f;
      for (int d = 0; d < 64; d++) t += cb[d];
      kk = fmaf(csum[p], t, kk);
    }
    sh_K[tid] = kk;
  }
  float cs = 0.f, cq = 0.f;
  #pragma unroll
  for (int i = 0; i < CH; i++){
    float2 a = __ldg(&g_q1[b*CH + i]);
    float2 c = __ldg(&g_q2[b*CH + i]);
    float2 d = __ldg(&g_q3[b*CH + i]);
    cs += a.x + c.x + d.x; cq += a.y + c.y + d.y;
  }
  float mc = cs*INV_N12;
  float icat = rsqrtf(fmaf(-mc, mc, cq*INV_N12) + EPSF);
  __syncthreads();

  const float4* zsrc = reinterpret_cast<const float4*>(g_z + (size_t)b*AA*16);
  float sz = 0.f, qz = 0.f;
  for (int idx = tid; idx < AA*4; idx += NTH){
    float4 v = zsrc[idx];
    int a = idx >> 2, o4 = (idx & 3)*4;
    v.x = icat*(v.x - mc*sh_K[o4+0]);
    v.y = icat*(v.y - mc*sh_K[o4+1]);
    v.z = icat*(v.z - mc*sh_K[o4+2]);
    v.w = icat*(v.w - mc*sh_K[o4+3]);
    float* dst = sh_z + a*17 + o4;
    dst[0] = v.x; dst[1] = v.y; dst[2] = v.z; dst[3] = v.w;
    sz += v.x+v.y+v.z+v.w;
    qz = fmaf(v.x,v.x, fmaf(v.y,v.y, fmaf(v.z,v.z, fmaf(v.w,v.w, qz))));
  }
  blockReduce2(sz, qz, sh_red);
  const float invN4 = 1.f/(16.f*(float)AA);
  float m4 = sz*invN4;
  float i4 = rsqrtf(fmaf(-m4, m4, qz*invN4) + EPSF);

  float rv[2]; float sr = 0.f, qr = 0.f;
  #pragma unroll
  for (int j = 0; j < 2; j++){
    int a = tid + j*NTH;
    float r = sh_c3[16]*w[(size_t)b*AA + a];
    const float* zr = sh_z + a*17;
    #pragma unroll
    for (int o = 0; o < 16; o++)
      r = fmaf(sh_c3[o], (zr[o] - m4)*i4, r);
    rv[j] = r; sr += r; qr = fmaf(r, r, qr);
  }
  blockReduce2(sr, qr, sh_red);
  float m5 = sr*(1.f/(float)AA);
  float i5 = rsqrtf(fmaf(-m5, m5, qr*(1.f/(float)AA)) + EPSF);
  #pragma unroll
  for (int j = 0; j < 2; j++)
    out[(size_t)b*AA + tid + j*NTH] = (rv[j] - m5)*i5;
}

extern "C" void kernel_launch(void* const* d_in, const int* in_sizes, int n_in,
                              void* d_out, int out_size)
{
  (void)in_sizes; (void)n_in; (void)out_size;
  const float* s    = (const float*)d_in[0];
  const float* w    = (const float*)d_in[1];
  const float* d1w1 = (const float*)d_in[2];
  const float* d1w2 = (const float*)d_in[3];
  const float* d2w1 = (const float*)d_in[4];
  const float* d2w2 = (const float*)d_in[5];
  const float* d3w1 = (const float*)d_in[6];
  const float* d3w2 = (const float*)d_in[7];
  const float* cw   = (const float*)d_in[8];
  const float* c2w  = (const float*)d_in[9];
  const float* c3w  = (const float*)d_in[10];
  float* out = (float*)d_out;

  k_statsA<<<BB*CH, NTH>>>(s, d1w1);
  k_passB <<<BB*CH, NTH>>>(s, d1w2, d2w1);
  k_passC <<<BB*CH, NTH>>>(s, d2w2, d3w1, cw);
  k_passD <<<BB*CH, NTH>>>(d3w2, cw, c2w);
  k_final <<<BB,    NTH>>>(w, cw, c2w, c3w, out);
}